// round 7
// baseline (speedup 1.0000x reference)
#include <cuda_runtime.h>
#include <cuda_bf16.h>
#include <cstdint>

#define B_    4
#define C_    384
#define HW_   16384
#define NH_   8
#define HD_   48
#define OC3_  1152
#define NSPLIT 8
#define KSPLIT_ 2048

// ---------------------------------------------------------------------------
// Scratch (device globals — no allocation allowed). bf16 pairs stored as u32.
// ---------------------------------------------------------------------------
__device__ uint32_t g_x_hi[(size_t)B_ * C_ * HW_ / 2];
__device__ uint32_t g_x_lo[(size_t)B_ * C_ * HW_ / 2];
__device__ uint32_t g_qkv_hi[(size_t)B_ * OC3_ * HW_ / 2];
__device__ uint32_t g_qkv_lo[(size_t)B_ * OC3_ * HW_ / 2];
__device__ uint32_t g_w_hi[OC3_ * C_ / 2];
__device__ uint32_t g_w_lo[OC3_ * C_ / 2];
__device__ uint32_t g_weff_hi[(size_t)B_ * C_ * C_ / 2];
__device__ uint32_t g_weff_lo[(size_t)B_ * C_ * C_ / 2];
__device__ float    g_gram[(size_t)NSPLIT * B_ * NH_ * 96 * 96];

// ---------------------------------------------------------------------------
// Helpers
// ---------------------------------------------------------------------------
__device__ __forceinline__ uint32_t smem_u32(const void* p) {
    uint32_t a;
    asm("{ .reg .u64 t; cvta.to.shared.u64 t, %1; cvt.u32.u64 %0, t; }" : "=r"(a) : "l"(p));
    return a;
}

// fp32 pair -> bf16x2 hi (exact truncation) and bf16x2 lo (rounded residual)
__device__ __forceinline__ void split2(uint32_t& hi, uint32_t& lo, float f0, float f1) {
    uint32_t u0 = __float_as_uint(f0), u1 = __float_as_uint(f1);
    asm("prmt.b32 %0, %1, %2, 0x7632;" : "=r"(hi) : "r"(u0), "r"(u1));
    float h0 = __uint_as_float(u0 & 0xFFFF0000u);
    float h1 = __uint_as_float(u1 & 0xFFFF0000u);
    float l0 = f0 - h0, l1 = f1 - h1;
    asm("cvt.rn.bf16x2.f32 %0, %1, %2;" : "=r"(lo) : "f"(l1), "f"(l0));
}

__device__ __forceinline__ void ldsm4(uint32_t* r, uint32_t addr) {
    asm volatile("ldmatrix.sync.aligned.m8n8.x4.shared.b16 {%0,%1,%2,%3}, [%4];"
                 : "=r"(r[0]), "=r"(r[1]), "=r"(r[2]), "=r"(r[3]) : "r"(addr));
}
__device__ __forceinline__ void ldsm4t(uint32_t* r, uint32_t addr) {
    asm volatile("ldmatrix.sync.aligned.m8n8.x4.trans.shared.b16 {%0,%1,%2,%3}, [%4];"
                 : "=r"(r[0]), "=r"(r[1]), "=r"(r[2]), "=r"(r[3]) : "r"(addr));
}
__device__ __forceinline__ void ldsm2(uint32_t* r, uint32_t addr) {
    asm volatile("ldmatrix.sync.aligned.m8n8.x2.shared.b16 {%0,%1}, [%2];"
                 : "=r"(r[0]), "=r"(r[1]) : "r"(addr));
}
__device__ __forceinline__ void mma16816(float* d, const uint32_t* a, const uint32_t* b) {
    asm volatile(
        "mma.sync.aligned.m16n8k16.row.col.f32.bf16.bf16.f32 "
        "{%0,%1,%2,%3}, {%4,%5,%6,%7}, {%8,%9}, {%0,%1,%2,%3};"
        : "+f"(d[0]), "+f"(d[1]), "+f"(d[2]), "+f"(d[3])
        : "r"(a[0]), "r"(a[1]), "r"(a[2]), "r"(a[3]), "r"(b[0]), "r"(b[1]));
}

__device__ __forceinline__ void cpa16(uint32_t dst, const void* src) {
    asm volatile("cp.async.cg.shared.global [%0], [%1], 16;" :: "r"(dst), "l"(src) : "memory");
}
#define CPA_COMMIT() asm volatile("cp.async.commit_group;" ::: "memory")
#define CPA_WAIT1()  asm volatile("cp.async.wait_group 1;"  ::: "memory")
#define CPA_WAIT0()  asm volatile("cp.async.wait_group 0;"  ::: "memory")

// ============================================================================
// split_planes: fp32 -> bf16 hi/lo planes (pairwise)
// ============================================================================
__global__ void __launch_bounds__(256)
split_planes(const float2* __restrict__ src, uint32_t* __restrict__ hp,
             uint32_t* __restrict__ lp, int n)
{
    for (int i = blockIdx.x * blockDim.x + threadIdx.x; i < n; i += gridDim.x * blockDim.x) {
        float2 v = src[i];
        uint32_t h, l;
        split2(h, l, v.x, v.y);
        hp[i] = h; lp[i] = l;
    }
}

// ===========================================================================
// GEMM: C[b] = A[b] (MxK) * B[b] (KxN), operands pre-split bf16 hi/lo planes.
// Tile 128x256, BK=32, 8 warps (2x4, warp tile 64x64), 3-stage cp.async.
// SMEM stage: A hi/lo [128][40]h, B hi/lo [32][264]h  (54272 B)
// mode 0: write C as bf16 hi/lo planes.  mode 1: write fp32 + bias.
// ===========================================================================
#define AH_OFF 0
#define AL_OFF 10240
#define BH_OFF 20480
#define BL_OFF 37376
#define STG_SZ 54272
#define GEMM_SMEM (3 * STG_SZ)   // 162816; epilogue reuse needs 133120 <= this

__global__ void __launch_bounds__(256, 1)
gemm_cp(const __nv_bfloat16* __restrict__ Ah, const __nv_bfloat16* __restrict__ Al,
        const __nv_bfloat16* __restrict__ Bh, const __nv_bfloat16* __restrict__ Bl,
        int M, int N, int K, long long sA, long long sB,
        int mode,
        uint32_t* __restrict__ Ohi, uint32_t* __restrict__ Olo, long long sOu,
        float* __restrict__ Of, long long sC, const float* __restrict__ bias)
{
    extern __shared__ char smem[];
    const uint32_t sb = smem_u32(smem);
    const int tid = threadIdx.x;
    const int wid = tid >> 5, lane = tid & 31;

    const int z = blockIdx.z;
    Ah += (size_t)z * sA;  Al += (size_t)z * sA;
    Bh += (size_t)z * sB;  Bl += (size_t)z * sB;
    const int tm = blockIdx.x * 128, tn = blockIdx.y * 256;
    const int warp_m = (wid >> 2) * 64, warp_n = (wid & 3) * 64;

    float acc[4][8][4];
#pragma unroll
    for (int i = 0; i < 4; i++)
#pragma unroll
        for (int j = 0; j < 8; j++)
#pragma unroll
            for (int p = 0; p < 4; p++) acc[i][j][p] = 0.0f;

    auto ISSUE = [&](int s, int c) {
        const int k0 = c * 32;
        const uint32_t stg = sb + s * STG_SZ;
        // A: 2 planes x 128 rows x 4 chunks = 1024
#pragma unroll
        for (int i = 0; i < 4; i++) {
            int id = tid + 256 * i;
            int pl = id >> 9, rem = id & 511, row = rem >> 2, ch = rem & 3;
            const __nv_bfloat16* src = (pl ? Al : Ah) + (size_t)(tm + row) * K + k0 + ch * 8;
            cpa16(stg + AH_OFF + pl * (AL_OFF - AH_OFF) + (uint32_t)((row * 40 + ch * 8) << 1), src);
        }
        // B: 2 planes x 32 rows x 32 chunks = 2048
#pragma unroll
        for (int i = 0; i < 8; i++) {
            int id = tid + 256 * i;
            int pl = id >> 10, rem = id & 1023, row = rem >> 5, ch = rem & 31;
            const __nv_bfloat16* src = (pl ? Bl : Bh) + (size_t)(k0 + row) * N + tn + ch * 8;
            cpa16(stg + BH_OFF + pl * (BL_OFF - BH_OFF) + (uint32_t)((row * 264 + ch * 8) << 1), src);
        }
        CPA_COMMIT();
    };

    auto MMASTEP = [&](int s, int ks) {
        const uint32_t stg = sb + s * STG_SZ;
        uint32_t bh[8][2], bl[8][2];
        {
            uint32_t krow = (uint32_t)(ks * 16 + (lane & 7) + (((lane >> 3) & 1) << 3));
            uint32_t ncol = (uint32_t)(warp_n + ((lane >> 4) << 3));
            uint32_t bd  = stg + BH_OFF + ((krow * 264 + ncol) << 1);
            uint32_t bdl = bd + (BL_OFF - BH_OFF);
            uint32_t r4[4];
#pragma unroll
            for (int j = 0; j < 4; j++) {
                ldsm4t(r4, bd + j * 32);
                bh[2 * j][0] = r4[0]; bh[2 * j][1] = r4[1];
                bh[2 * j + 1][0] = r4[2]; bh[2 * j + 1][1] = r4[3];
            }
#pragma unroll
            for (int j = 0; j < 4; j++) {
                ldsm4t(r4, bdl + j * 32);
                bl[2 * j][0] = r4[0]; bl[2 * j][1] = r4[1];
                bl[2 * j + 1][0] = r4[2]; bl[2 * j + 1][1] = r4[3];
            }
        }
        const uint32_t arow = (uint32_t)(warp_m + (lane & 15));
        const uint32_t akoff = (uint32_t)(ks * 16 + ((lane >> 4) << 3));
#pragma unroll
        for (int mf = 0; mf < 4; mf++) {
            uint32_t ah[4], al[4];
            uint32_t ad = stg + AH_OFF + (((arow + mf * 16) * 40 + akoff) << 1);
            ldsm4(ah, ad);
            ldsm4(al, ad + (AL_OFF - AH_OFF));
#pragma unroll
            for (int nf = 0; nf < 8; nf++) {
                mma16816(acc[mf][nf], ah, bh[nf]);
                mma16816(acc[mf][nf], ah, bl[nf]);
                mma16816(acc[mf][nf], al, bh[nf]);
            }
        }
    };

    const int NC = K >> 5;   // 12 for K=384
    ISSUE(0, 0);
    ISSUE(1, 1);
    for (int c = 0; c < NC; c++) {
        const int s = c % 3;
        if (c == NC - 1) { CPA_WAIT0(); } else { CPA_WAIT1(); }
        __syncthreads();
        if (c + 2 < NC) ISSUE((c + 2) % 3, c + 2);
        MMASTEP(s, 0);
        MMASTEP(s, 1);
    }
    __syncthreads();   // before reusing smem for epilogue staging

    // Stage acc into fp32 smem [128][260]
    float* cs = reinterpret_cast<float*>(smem);
    const int g = lane >> 2, t2 = (lane & 3) * 2;
#pragma unroll
    for (int mf = 0; mf < 4; mf++)
#pragma unroll
        for (int nf = 0; nf < 8; nf++) {
            int r0 = warp_m + mf * 16 + g;
            int c0 = warp_n + nf * 8 + t2;
            cs[r0 * 260 + c0]           = acc[mf][nf][0];
            cs[r0 * 260 + c0 + 1]       = acc[mf][nf][1];
            cs[(r0 + 8) * 260 + c0]     = acc[mf][nf][2];
            cs[(r0 + 8) * 260 + c0 + 1] = acc[mf][nf][3];
        }
    __syncthreads();

    const int r = tid >> 1, cb = (tid & 1) * 128;
    const float* ip = &cs[r * 260 + cb];
    if (mode == 1) {
        float* op = Of + (size_t)z * sC + (size_t)(tm + r) * N + tn + cb;
        const float bval = bias[tm + r];
#pragma unroll
        for (int j = 0; j < 32; j++) {
            float4 v = make_float4(ip[4 * j] + bval, ip[4 * j + 1] + bval,
                                   ip[4 * j + 2] + bval, ip[4 * j + 3] + bval);
            reinterpret_cast<float4*>(op)[j] = v;
        }
    } else {
        size_t ro = (size_t)z * sOu + (size_t)(tm + r) * (N >> 1) + ((size_t)(tn + cb) >> 1);
        uint4* ph = reinterpret_cast<uint4*>(Ohi + ro);
        uint4* plp = reinterpret_cast<uint4*>(Olo + ro);
#pragma unroll
        for (int j = 0; j < 16; j++) {
            uint32_t h0, l0, h1, l1, h2, l2, h3, l3;
            split2(h0, l0, ip[8 * j + 0], ip[8 * j + 1]);
            split2(h1, l1, ip[8 * j + 2], ip[8 * j + 3]);
            split2(h2, l2, ip[8 * j + 4], ip[8 * j + 5]);
            split2(h3, l3, ip[8 * j + 6], ip[8 * j + 7]);
            ph[j]  = make_uint4(h0, h1, h2, h3);
            plp[j] = make_uint4(l0, l1, l2, l3);
        }
    }
}

// ===========================================================================
// Gram: per (b, head, split), G_partial = Y Y^T, Y = [q;k] (96 x KSPLIT_),
// read from qkv hi/lo planes via cp.async. Stage: [96][72]h x2 planes (27648B),
// 3 stages. Warps 2x4: warp tile 48x24 (3x3 frags). BK=64 per chunk.
// ===========================================================================
#define YH_OFF 0
#define YL_OFF 13824
#define GSTG 27648
#define GRAM_SMEM (3 * GSTG)

__global__ void __launch_bounds__(256, 1)
gram_cp(const __nv_bfloat16* __restrict__ Qh, const __nv_bfloat16* __restrict__ Ql)
{
    extern __shared__ char smem[];
    const uint32_t sb = smem_u32(smem);
    const int tid = threadIdx.x;
    const int wid = tid >> 5, lane = tid & 31;
    const int split = blockIdx.x;
    const int bh = blockIdx.y;
    const int b = bh >> 3, h = bh & 7;
    const size_t bofs = (size_t)b * OC3_ * HW_;
    const int kbase = split * KSPLIT_;
    const int warp_m = (wid >> 2) * 48, warp_n = (wid & 3) * 24;

    float acc[3][3][4];
#pragma unroll
    for (int i = 0; i < 3; i++)
#pragma unroll
        for (int j = 0; j < 3; j++)
#pragma unroll
            for (int p = 0; p < 4; p++) acc[i][j][p] = 0.0f;

    auto ISSUE = [&](int s, int c) {
        const int k0 = kbase + c * 64;
        const uint32_t stg = sb + s * GSTG;
        // 2 planes x 96 rows x 8 chunks = 1536
#pragma unroll
        for (int i = 0; i < 6; i++) {
            int id = tid + 256 * i;
            int pl = (id >= 768), rem = id - pl * 768;
            int row = rem >> 3, ch = rem & 7;
            int chn = (row < 48) ? (h * HD_ + row) : (C_ + h * HD_ + (row - 48));
            const __nv_bfloat16* src = (pl ? Ql : Qh) + bofs + (size_t)chn * HW_ + k0 + ch * 8;
            cpa16(stg + pl * (YL_OFF - YH_OFF) + (uint32_t)((row * 72 + ch * 8) << 1), src);
        }
        CPA_COMMIT();
    };

    auto MMASTEP = [&](int s, int ks) {
        const uint32_t stg = sb + s * GSTG;
        uint32_t ah[3][4], al[3][4], bhf[3][2], blf[3][2];
        const uint32_t koff = (uint32_t)(ks * 16 + ((lane >> 4) << 3));
#pragma unroll
        for (int mf = 0; mf < 3; mf++) {
            uint32_t ad = stg + (((uint32_t)(warp_m + mf * 16 + (lane & 15)) * 72 + koff) << 1);
            ldsm4(ah[mf], ad);
            ldsm4(al[mf], ad + (YL_OFF - YH_OFF));
        }
        {
            uint32_t bd = stg + (((uint32_t)(warp_n + (lane & 15)) * 72 + koff) << 1);
            uint32_t r4[4];
            ldsm4(r4, bd);
            bhf[0][0] = r4[0]; bhf[0][1] = r4[2]; bhf[1][0] = r4[1]; bhf[1][1] = r4[3];
            ldsm4(r4, bd + (YL_OFF - YH_OFF));
            blf[0][0] = r4[0]; blf[0][1] = r4[2]; blf[1][0] = r4[1]; blf[1][1] = r4[3];
            uint32_t k2 = (uint32_t)(ks * 16 + (((lane >> 3) & 1) << 3));
            uint32_t bd2 = stg + (((uint32_t)(warp_n + 16 + (lane & 7)) * 72 + k2) << 1);
            uint32_t r2[2];
            ldsm2(r2, bd2);
            bhf[2][0] = r2[0]; bhf[2][1] = r2[1];
            ldsm2(r2, bd2 + (YL_OFF - YH_OFF));
            blf[2][0] = r2[0]; blf[2][1] = r2[1];
        }
#pragma unroll
        for (int mf = 0; mf < 3; mf++)
#pragma unroll
            for (int nf = 0; nf < 3; nf++) {
                mma16816(acc[mf][nf], ah[mf], bhf[nf]);
                mma16816(acc[mf][nf], ah[mf], blf[nf]);
                mma16816(acc[mf][nf], al[mf], bhf[nf]);
            }
    };

    const int NC = KSPLIT_ >> 6;   // 32
    ISSUE(0, 0);
    ISSUE(1, 1);
    for (int c = 0; c < NC; c++) {
        const int s = c % 3;
        if (c == NC - 1) { CPA_WAIT0(); } else { CPA_WAIT1(); }
        __syncthreads();
        if (c + 2 < NC) ISSUE((c + 2) % 3, c + 2);
        MMASTEP(s, 0); MMASTEP(s, 1); MMASTEP(s, 2); MMASTEP(s, 3);
    }

    float* gout = g_gram + ((size_t)split * (B_ * NH_) + bh) * 96 * 96;
    const int g = lane >> 2, t2 = (lane & 3) * 2;
#pragma unroll
    for (int mf = 0; mf < 3; mf++)
#pragma unroll
        for (int nf = 0; nf < 3; nf++) {
            int r0 = warp_m + mf * 16 + g;
            int c0 = warp_n + nf * 8 + t2;
            gout[r0 * 96 + c0]           = acc[mf][nf][0];
            gout[r0 * 96 + c0 + 1]       = acc[mf][nf][1];
            gout[(r0 + 8) * 96 + c0]     = acc[mf][nf][2];
            gout[(r0 + 8) * 96 + c0 + 1] = acc[mf][nf][3];
        }
}

// ============================================================================
// Fused attention + W_eff (per b,head): gram-reduce -> softmax -> fold into
// proj_w slice; writes weff as bf16 hi/lo planes.
// ============================================================================
#define AW_SG   0
#define AW_SINV 2304
#define AW_SATT 2400
#define AW_SPW  4704
#define AW_SMEM ((AW_SPW + 384 * 49) * 4)

__global__ void __launch_bounds__(256)
attn_weff_kernel(const float* __restrict__ temperature,
                 const float* __restrict__ proj_w)
{
    extern __shared__ float sm[];
    float* sG    = sm + AW_SG;
    float* sInv  = sm + AW_SINV;
    float* sAttn = sm + AW_SATT;
    float* spw   = sm + AW_SPW;

    const int bh = blockIdx.x;
    const int b = bh >> 3, h = bh & 7;
    const int tid = threadIdx.x;

    for (int idx = tid; idx < 48 * 48; idx += 256) {
        int d = idx / 48, e = idx % 48;
        float s = 0.0f;
#pragma unroll
        for (int sp = 0; sp < NSPLIT; sp++)
            s += g_gram[((size_t)sp * (B_ * NH_) + bh) * 96 * 96 + d * 96 + 48 + e];
        sG[idx] = s;
    }
    if (tid < 96) {
        float ss = 0.0f;
#pragma unroll
        for (int sp = 0; sp < NSPLIT; sp++)
            ss += g_gram[((size_t)sp * (B_ * NH_) + bh) * 96 * 96 + tid * 96 + tid];
        sInv[tid] = 1.0f / fmaxf(sqrtf(ss), 1e-12f);
    }
    for (int idx = tid; idx < 384 * 12; idx += 256) {
        int o = idx / 12, d4 = (idx % 12) * 4;
        float4 v = *reinterpret_cast<const float4*>(&proj_w[(size_t)o * C_ + h * 48 + d4]);
        float* dst = &spw[o * 49 + d4];
        dst[0] = v.x; dst[1] = v.y; dst[2] = v.z; dst[3] = v.w;
    }
    __syncthreads();

    const float temp = temperature[h];
    if (tid < 48) {
        int d = tid;
        float l[48];
        float mx = -1e30f;
#pragma unroll
        for (int e = 0; e < 48; e++) {
            float v = sG[d * 48 + e] * sInv[d] * sInv[48 + e] * temp;
            l[e] = v;
            mx = fmaxf(mx, v);
        }
        float sum = 0.0f;
#pragma unroll
        for (int e = 0; e < 48; e++) { l[e] = expf(l[e] - mx); sum += l[e]; }
        float inv = 1.0f / sum;
#pragma unroll
        for (int e = 0; e < 48; e++) sAttn[d * 48 + e] = l[e] * inv;
    }
    __syncthreads();

    for (int o = tid; o < 384; o += 256) {
        const float* pw = &spw[o * 49];
        uint32_t* whi = g_weff_hi + ((size_t)b * C_ + o) * (C_ >> 1) + h * 24;
        uint32_t* wlo = g_weff_lo + ((size_t)b * C_ + o) * (C_ >> 1) + h * 24;
#pragma unroll
        for (int eb = 0; eb < 6; eb++) {
            float a0 = 0, a1 = 0, a2 = 0, a3 = 0, a4 = 0, a5 = 0, a6 = 0, a7 = 0;
#pragma unroll 8
            for (int d = 0; d < 48; d++) {
                float p = pw[d];
                const float* ar = &sAttn[d * 48 + eb * 8];
                a0 += p * ar[0]; a1 += p * ar[1]; a2 += p * ar[2]; a3 += p * ar[3];
                a4 += p * ar[4]; a5 += p * ar[5]; a6 += p * ar[6]; a7 += p * ar[7];
            }
            uint32_t hh, ll;
            split2(hh, ll, a0, a1); whi[eb * 4 + 0] = hh; wlo[eb * 4 + 0] = ll;
            split2(hh, ll, a2, a3); whi[eb * 4 + 1] = hh; wlo[eb * 4 + 1] = ll;
            split2(hh, ll, a4, a5); whi[eb * 4 + 2] = hh; wlo[eb * 4 + 2] = ll;
            split2(hh, ll, a6, a7); whi[eb * 4 + 3] = hh; wlo[eb * 4 + 3] = ll;
        }
    }
}

// ============================================================================
extern "C" void kernel_launch(void* const* d_in, const int* in_sizes, int n_in,
                              void* d_out, int out_size)
{
    const float* x           = (const float*)d_in[0];
    const float* qkv_w       = (const float*)d_in[1];
    const float* proj_w      = (const float*)d_in[2];
    const float* proj_b      = (const float*)d_in[3];
    const float* temperature = (const float*)d_in[4];
    float* out = (float*)d_out;

    void* p;
    cudaGetSymbolAddress(&p, g_x_hi);    uint32_t* x_hi   = (uint32_t*)p;
    cudaGetSymbolAddress(&p, g_x_lo);    uint32_t* x_lo   = (uint32_t*)p;
    cudaGetSymbolAddress(&p, g_qkv_hi);  uint32_t* qkv_hi = (uint32_t*)p;
    cudaGetSymbolAddress(&p, g_qkv_lo);  uint32_t* qkv_lo = (uint32_t*)p;
    cudaGetSymbolAddress(&p, g_w_hi);    uint32_t* w_hi   = (uint32_t*)p;
    cudaGetSymbolAddress(&p, g_w_lo);    uint32_t* w_lo   = (uint32_t*)p;
    cudaGetSymbolAddress(&p, g_weff_hi); uint32_t* we_hi  = (uint32_t*)p;
    cudaGetSymbolAddress(&p, g_weff_lo); uint32_t* we_lo  = (uint32_t*)p;

    cudaFuncSetAttribute((const void*)gemm_cp,
                         cudaFuncAttributeMaxDynamicSharedMemorySize, GEMM_SMEM);
    cudaFuncSetAttribute((const void*)gram_cp,
                         cudaFuncAttributeMaxDynamicSharedMemorySize, GRAM_SMEM);
    cudaFuncSetAttribute((const void*)attn_weff_kernel,
                         cudaFuncAttributeMaxDynamicSharedMemorySize, AW_SMEM);

    // K0: split x and qkv_w into bf16 hi/lo planes
    split_planes<<<2048, 256>>>((const float2*)x, x_hi, x_lo, B_ * C_ * HW_ / 2);
    split_planes<<<864, 256>>>((const float2*)qkv_w, w_hi, w_lo, OC3_ * C_ / 2);

    // K1: qkv = qkv_w @ x[b]  -> bf16 hi/lo planes
    gemm_cp<<<dim3(OC3_ / 128, HW_ / 256, B_), 256, GEMM_SMEM>>>(
        (const __nv_bfloat16*)w_hi, (const __nv_bfloat16*)w_lo,
        (const __nv_bfloat16*)x_hi, (const __nv_bfloat16*)x_lo,
        OC3_, HW_, C_, 0LL, (long long)C_ * HW_,
        0, qkv_hi, qkv_lo, (long long)OC3_ * HW_ / 2,
        nullptr, 0LL, nullptr);

    // K2: split-K Gram of [q;k] per (b, head)
    gram_cp<<<dim3(NSPLIT, B_ * NH_), 256, GRAM_SMEM>>>(
        (const __nv_bfloat16*)qkv_hi, (const __nv_bfloat16*)qkv_lo);

    // K3: fused norms + softmax + attn-fold into projection weights (hi/lo out)
    attn_weff_kernel<<<B_ * NH_, 256, AW_SMEM>>>(temperature, proj_w);

    // K4: out = W_eff[b] @ v[b] + proj_b   (fp32 out)
    gemm_cp<<<dim3(C_ / 128, HW_ / 256, B_), 256, GEMM_SMEM>>>(
        (const __nv_bfloat16*)we_hi, (const __nv_bfloat16*)we_lo,
        (const __nv_bfloat16*)qkv_hi + (size_t)2 * C_ * HW_,
        (const __nv_bfloat16*)qkv_lo + (size_t)2 * C_ * HW_,
        C_, HW_, C_, (long long)C_ * C_, (long long)OC3_ * HW_,
        1, nullptr, nullptr, 0LL,
        out, (long long)C_ * HW_, proj_b);
}

// round 9
// speedup vs baseline: 1.4904x; 1.4904x over previous
#include <cuda_runtime.h>
#include <cuda_bf16.h>
#include <cstdint>

#define B_    4
#define C_    384
#define HW_   16384
#define NH_   8
#define HD_   48
#define NS2   16            // split-K for X2
#define XK_   (HW_ / NS2)   // 1024

typedef unsigned long long u64;

// ---------------------------------------------------------------------------
// Scratch (device globals — no allocation allowed)
// ---------------------------------------------------------------------------
__device__ uint32_t g_x_hi[(size_t)B_ * C_ * HW_ / 2];     // x as bf16 hi plane
__device__ uint32_t g_x_lo[(size_t)B_ * C_ * HW_ / 2];     // x residual plane
__device__ float    g_x2p[(size_t)NS2 * B_ * 6 * 128 * 128]; // X2 partials (upper blocks)
__device__ float    g_x2[(size_t)B_ * C_ * C_];            // X2 full (mirrored)
__device__ float    g_T[(size_t)B_ * NH_ * 96 * C_];       // T = Wqk_h · X2
__device__ float    g_weff[(size_t)B_ * C_ * C_];          // P with attn folded
__device__ uint32_t g_wf_hi[(size_t)B_ * C_ * C_ / 2];     // W_final hi plane
__device__ uint32_t g_wf_lo[(size_t)B_ * C_ * C_ / 2];     // W_final lo plane

// ---------------------------------------------------------------------------
// Helpers
// ---------------------------------------------------------------------------
__device__ __forceinline__ uint32_t smem_u32(const void* p) {
    uint32_t a;
    asm("{ .reg .u64 t; cvta.to.shared.u64 t, %1; cvt.u32.u64 %0, t; }" : "=r"(a) : "l"(p));
    return a;
}
// fp32 pair -> bf16x2 hi (exact truncation) and bf16x2 lo (rounded residual)
__device__ __forceinline__ void split2(uint32_t& hi, uint32_t& lo, float f0, float f1) {
    uint32_t u0 = __float_as_uint(f0), u1 = __float_as_uint(f1);
    asm("prmt.b32 %0, %1, %2, 0x7632;" : "=r"(hi) : "r"(u0), "r"(u1));
    float h0 = __uint_as_float(u0 & 0xFFFF0000u);
    float h1 = __uint_as_float(u1 & 0xFFFF0000u);
    float l0 = f0 - h0, l1 = f1 - h1;
    asm("cvt.rn.bf16x2.f32 %0, %1, %2;" : "=r"(lo) : "f"(l1), "f"(l0));
}
__device__ __forceinline__ void ldsm4(uint32_t* r, uint32_t addr) {
    asm volatile("ldmatrix.sync.aligned.m8n8.x4.shared.b16 {%0,%1,%2,%3}, [%4];"
                 : "=r"(r[0]), "=r"(r[1]), "=r"(r[2]), "=r"(r[3]) : "r"(addr));
}
__device__ __forceinline__ void ldsm4t(uint32_t* r, uint32_t addr) {
    asm volatile("ldmatrix.sync.aligned.m8n8.x4.trans.shared.b16 {%0,%1,%2,%3}, [%4];"
                 : "=r"(r[0]), "=r"(r[1]), "=r"(r[2]), "=r"(r[3]) : "r"(addr));
}
__device__ __forceinline__ void mma16816(float* d, const uint32_t* a, const uint32_t* b) {
    asm volatile(
        "mma.sync.aligned.m16n8k16.row.col.f32.bf16.bf16.f32 "
        "{%0,%1,%2,%3}, {%4,%5,%6,%7}, {%8,%9}, {%0,%1,%2,%3};"
        : "+f"(d[0]), "+f"(d[1]), "+f"(d[2]), "+f"(d[3])
        : "r"(a[0]), "r"(a[1]), "r"(a[2]), "r"(a[3]), "r"(b[0]), "r"(b[1]));
}
__device__ __forceinline__ void cpa16(uint32_t dst, const void* src) {
    asm volatile("cp.async.cg.shared.global [%0], [%1], 16;" :: "r"(dst), "l"(src) : "memory");
}
#define CPA_COMMIT() asm volatile("cp.async.commit_group;" ::: "memory")
#define CPA_WAIT1()  asm volatile("cp.async.wait_group 1;"  ::: "memory")
#define CPA_WAIT0()  asm volatile("cp.async.wait_group 0;"  ::: "memory")

// packed f32x2 for the small fp32 GEMM
__device__ __forceinline__ u64 pk2(float lo, float hi) {
    u64 r; asm("mov.b64 %0, {%1,%2};" : "=l"(r) : "f"(lo), "f"(hi)); return r;
}
__device__ __forceinline__ void upk2(u64 v, float& lo, float& hi) {
    asm("mov.b64 {%0,%1}, %2;" : "=f"(lo), "=f"(hi) : "l"(v));
}
__device__ __forceinline__ u64 fma2(u64 a, u64 b, u64 c) {
    u64 d; asm("fma.rn.f32x2 %0, %1, %2, %3;" : "=l"(d) : "l"(a), "l"(b), "l"(c)); return d;
}

// ============================================================================
// K0: fp32 -> bf16 hi/lo planes
// ============================================================================
__global__ void __launch_bounds__(256)
split_planes(const float2* __restrict__ src, uint32_t* __restrict__ hp,
             uint32_t* __restrict__ lp, int n)
{
    for (int i = blockIdx.x * blockDim.x + threadIdx.x; i < n; i += gridDim.x * blockDim.x) {
        float2 v = src[i];
        uint32_t h, l;
        split2(h, l, v.x, v.y);
        hp[i] = h; lp[i] = l;
    }
}

// ============================================================================
// K1: X2 partials. Per (b, upper-block-pair, split): P = Xa · Xb^T over XK_.
// Block tile 128x128, warps 2x4 (64x32), BK=64, 3-stage cp.async.
// Stage: A hi/lo + B hi/lo, each [128][72] halves -> 4*18432 = 73728 B.
// ============================================================================
#define XT 18432
#define XSTG (4 * XT)
#define X2_SMEM (3 * XSTG)   // 221184

__constant__ int c_BI[6] = {0, 0, 0, 1, 1, 2};
__constant__ int c_BJ[6] = {0, 1, 2, 1, 2, 2};

__global__ void __launch_bounds__(256, 1)
x2_cp(const __nv_bfloat16* __restrict__ Xh, const __nv_bfloat16* __restrict__ Xl)
{
    extern __shared__ char smem[];
    const uint32_t sb = smem_u32(smem);
    const int tid = threadIdx.x;
    const int wid = tid >> 5, lane = tid & 31;
    const int bp = blockIdx.x / NS2, split = blockIdx.x % NS2;
    const int b = blockIdx.y;
    const int bi = c_BI[bp], bj = c_BJ[bp];
    const size_t xbase = (size_t)b * C_ * HW_;
    const int k0base = split * XK_;
    const int warp_m = (wid >> 2) * 64, warp_n = (wid & 3) * 32;

    float acc[4][4][4];
#pragma unroll
    for (int i = 0; i < 4; i++)
#pragma unroll
        for (int j = 0; j < 4; j++)
#pragma unroll
            for (int p = 0; p < 4; p++) acc[i][j][p] = 0.0f;

    auto ISSUE = [&](int s, int c) {
        const int k0 = k0base + c * 64;
        const uint32_t stg = sb + s * XSTG;
#pragma unroll
        for (int i = 0; i < 16; i++) {
            int id = tid + 256 * i;                // 0..4095
            int pt = id >> 10;                     // 0:A_hi 1:A_lo 2:B_hi 3:B_lo
            int rem = id & 1023;
            int row = rem >> 3, ch = rem & 7;
            int chan = ((pt < 2) ? bi : bj) * 128 + row;
            const __nv_bfloat16* src =
                ((pt & 1) ? Xl : Xh) + xbase + (size_t)chan * HW_ + k0 + ch * 8;
            cpa16(stg + pt * XT + (uint32_t)((row * 72 + ch * 8) << 1), src);
        }
        CPA_COMMIT();
    };

    auto MMASTEP = [&](int s, int ks) {
        const uint32_t stg = sb + s * XSTG;
        const uint32_t koff = (uint32_t)(ks * 16 + ((lane >> 4) << 3));
        uint32_t bh[4][2], bl[4][2];
        {
            uint32_t bd = stg + 2 * XT + (((uint32_t)(warp_n + (lane & 15)) * 72 + koff) << 1);
            uint32_t r4[4];
            ldsm4(r4, bd);
            bh[0][0] = r4[0]; bh[0][1] = r4[2]; bh[1][0] = r4[1]; bh[1][1] = r4[3];
            ldsm4(r4, bd + (72 * 16 << 1));   // rows +16
            bh[2][0] = r4[0]; bh[2][1] = r4[2]; bh[3][0] = r4[1]; bh[3][1] = r4[3];
            uint32_t bdl = bd + XT;
            ldsm4(r4, bdl);
            bl[0][0] = r4[0]; bl[0][1] = r4[2]; bl[1][0] = r4[1]; bl[1][1] = r4[3];
            ldsm4(r4, bdl + (72 * 16 << 1));
            bl[2][0] = r4[0]; bl[2][1] = r4[2]; bl[3][0] = r4[1]; bl[3][1] = r4[3];
        }
#pragma unroll
        for (int mf = 0; mf < 4; mf++) {
            uint32_t ah[4], al[4];
            uint32_t ad = stg + (((uint32_t)(warp_m + mf * 16 + (lane & 15)) * 72 + koff) << 1);
            ldsm4(ah, ad);
            ldsm4(al, ad + XT);
#pragma unroll
            for (int nf = 0; nf < 4; nf++) {
                mma16816(acc[mf][nf], ah, bh[nf]);
                mma16816(acc[mf][nf], ah, bl[nf]);
                mma16816(acc[mf][nf], al, bh[nf]);
            }
        }
    };

    const int NC = XK_ >> 6;   // 16
    ISSUE(0, 0);
    ISSUE(1, 1);
    for (int c = 0; c < NC; c++) {
        const int s = c % 3;
        if (c == NC - 1) { CPA_WAIT0(); } else { CPA_WAIT1(); }
        __syncthreads();
        if (c + 2 < NC) ISSUE((c + 2) % 3, c + 2);
        MMASTEP(s, 0); MMASTEP(s, 1); MMASTEP(s, 2); MMASTEP(s, 3);
    }

    float* pb = g_x2p + ((size_t)(b * NS2 + split) * 6 + bp) * 16384;
    const int g = lane >> 2, t2 = (lane & 3) * 2;
#pragma unroll
    for (int mf = 0; mf < 4; mf++)
#pragma unroll
        for (int nf = 0; nf < 4; nf++) {
            int r0 = warp_m + mf * 16 + g;
            int c0 = warp_n + nf * 8 + t2;
            pb[r0 * 128 + c0]           = acc[mf][nf][0];
            pb[r0 * 128 + c0 + 1]       = acc[mf][nf][1];
            pb[(r0 + 8) * 128 + c0]     = acc[mf][nf][2];
            pb[(r0 + 8) * 128 + c0 + 1] = acc[mf][nf][3];
        }
}

// ============================================================================
// K2: reduce split-K partials into full mirrored X2 [b][384][384]
// ============================================================================
__global__ void __launch_bounds__(256)
x2_reduce()
{
    int idx = blockIdx.x * 256 + threadIdx.x;          // 0 .. 4*384*384-1
    int b = idx / (C_ * C_);
    int rem = idx % (C_ * C_);
    int i = rem / C_, j = rem % C_;
    int bi = i >> 7, bj = j >> 7;
    int li, lj;
    int bp;
    if (bi <= bj) { bp = bi * 3 - bi * (bi - 1) / 2 + (bj - bi); li = i & 127; lj = j & 127; }
    else          { bp = bj * 3 - bj * (bj - 1) / 2 + (bi - bj); li = j & 127; lj = i & 127; }
    float s = 0.0f;
#pragma unroll
    for (int sp = 0; sp < NS2; sp++)
        s += g_x2p[((size_t)(b * NS2 + sp) * 6 + bp) * 16384 + li * 128 + lj];
    g_x2[idx] = s;
}

// ============================================================================
// K3: T[bh][96][384] = Wqk_h (96x384) · X2_b.  Grid (coltile 8, bh 32).
// Wqk rows: r<48 -> qkv_w[h*48+r], r>=48 -> qkv_w[384 + h*48 + (r-48)].
// ============================================================================
__global__ void __launch_bounds__(256)
tA_kernel(const float* __restrict__ qkv_w)
{
    __shared__ float sW[96][65];
    __shared__ float sX[64][49];
    const int ct = blockIdx.x;          // 48-col tile
    const int bh = blockIdx.y;
    const int b = bh >> 3, h = bh & 7;
    const int tid = threadIdx.x;
    const int r0 = (tid >> 4) * 6, c0 = (tid & 15) * 3;

    float acc[6][3];
#pragma unroll
    for (int i = 0; i < 6; i++)
#pragma unroll
        for (int j = 0; j < 3; j++) acc[i][j] = 0.0f;

    for (int kt = 0; kt < 6; kt++) {
        for (int idx = tid; idx < 96 * 64; idx += 256) {
            int r = idx >> 6, k = idx & 63;
            int wrow = (r < 48) ? (h * HD_ + r) : (C_ + h * HD_ + (r - 48));
            sW[r][k] = qkv_w[(size_t)wrow * C_ + kt * 64 + k];
        }
        for (int idx = tid; idx < 64 * 48; idx += 256) {
            int k = idx / 48, c = idx % 48;
            sX[k][c] = g_x2[(size_t)b * C_ * C_ + (size_t)(kt * 64 + k) * C_ + ct * 48 + c];
        }
        __syncthreads();
#pragma unroll 8
        for (int k = 0; k < 64; k++) {
            float xv0 = sX[k][c0], xv1 = sX[k][c0 + 1], xv2 = sX[k][c0 + 2];
#pragma unroll
            for (int i = 0; i < 6; i++) {
                float w = sW[r0 + i][k];
                acc[i][0] += w * xv0; acc[i][1] += w * xv1; acc[i][2] += w * xv2;
            }
        }
        __syncthreads();
    }
    float* T = g_T + (size_t)bh * 96 * C_;
#pragma unroll
    for (int i = 0; i < 6; i++)
#pragma unroll
        for (int j = 0; j < 3; j++)
            T[(size_t)(r0 + i) * C_ + ct * 48 + c0 + j] = acc[i][j];
}

// ============================================================================
// K4: per (b,h): Gqk + norms from T, softmax, fold attn into proj_w slice.
// Writes W_eff fp32 [b][384][h*48 .. +48].
// smem (floats): sWk[48*385] | sG[2304] | sInv[96] | sAttn[2304] | spw[384*49]
// ============================================================================
#define TB_OWK  0
#define TB_OG   18480
#define TB_OINV 20784
#define TB_OATT 20880
#define TB_OPW  23184
#define TB_SMEM ((TB_OPW + 384 * 49) * 4)   // 168000 B

__global__ void __launch_bounds__(256)
tB_kernel(const float* __restrict__ temperature,
          const float* __restrict__ proj_w,
          const float* __restrict__ qkv_w)
{
    extern __shared__ float sm[];
    float* sWk   = sm + TB_OWK;
    float* sG    = sm + TB_OG;
    float* sInv  = sm + TB_OINV;
    float* sAttn = sm + TB_OATT;
    float* spw   = sm + TB_OPW;

    const int bh = blockIdx.x;
    const int b = bh >> 3, h = bh & 7;
    const int tid = threadIdx.x;
    const float* T = g_T + (size_t)bh * 96 * C_;

    // load Wk rows (k-side of the head) and proj_w slice
    for (int idx = tid; idx < 48 * C_; idx += 256) {
        int e = idx / C_, k = idx % C_;
        sWk[e * 385 + k] = qkv_w[(size_t)(C_ + h * HD_ + e) * C_ + k];
    }
    for (int idx = tid; idx < 384 * 12; idx += 256) {
        int o = idx / 12, d4 = (idx % 12) * 4;
        float4 v = *reinterpret_cast<const float4*>(&proj_w[(size_t)o * C_ + h * 48 + d4]);
        float* dst = &spw[o * 49 + d4];
        dst[0] = v.x; dst[1] = v.y; dst[2] = v.z; dst[3] = v.w;
    }
    __syncthreads();

    // Gqk[d][e] = T[d] . Wk[e]
    for (int idx = tid; idx < 48 * 48; idx += 256) {
        int d = idx / 48, e = idx % 48;
        const float* tr = &T[(size_t)d * C_];
        const float* wr = &sWk[e * 385];
        float s = 0.0f;
#pragma unroll 8
        for (int k = 0; k < C_; k++) s += tr[k] * wr[k];
        sG[idx] = s;
    }
    // norms: q: T[d].Wq[d]   k: T[48+e].Wk[e]
    if (tid < 96) {
        float s = 0.0f;
        if (tid < 48) {
            const float* tr = &T[(size_t)tid * C_];
            const float* wq = &qkv_w[(size_t)(h * HD_ + tid) * C_];
#pragma unroll 8
            for (int k = 0; k < C_; k++) s += tr[k] * wq[k];
        } else {
            int e = tid - 48;
            const float* tr = &T[(size_t)(48 + e) * C_];
            const float* wr = &sWk[e * 385];
#pragma unroll 8
            for (int k = 0; k < C_; k++) s += tr[k] * wr[k];
        }
        sInv[tid] = 1.0f / fmaxf(sqrtf(s), 1e-12f);
    }
    __syncthreads();

    const float temp = temperature[h];
    if (tid < 48) {
        int d = tid;
        float l[48];
        float mx = -1e30f;
#pragma unroll
        for (int e = 0; e < 48; e++) {
            float v = sG[d * 48 + e] * sInv[d] * sInv[48 + e] * temp;
            l[e] = v;
            mx = fmaxf(mx, v);
        }
        float sum = 0.0f;
#pragma unroll
        for (int e = 0; e < 48; e++) { l[e] = expf(l[e] - mx); sum += l[e]; }
        float inv = 1.0f / sum;
#pragma unroll
        for (int e = 0; e < 48; e++) sAttn[d * 48 + e] = l[e] * inv;
    }
    __syncthreads();

    // W_eff[o][h*48+e] = sum_d proj_w[o][h*48+d] * attn[d][e]
    for (int o = tid; o < 384; o += 256) {
        const float* pw = &spw[o * 49];
        float* wout = &g_weff[((size_t)b * C_ + o) * C_ + h * 48];
#pragma unroll
        for (int eb = 0; eb < 6; eb++) {
            float a0 = 0, a1 = 0, a2 = 0, a3 = 0, a4 = 0, a5 = 0, a6 = 0, a7 = 0;
#pragma unroll 8
            for (int d = 0; d < 48; d++) {
                float p = pw[d];
                const float* ar = &sAttn[d * 48 + eb * 8];
                a0 += p * ar[0]; a1 += p * ar[1]; a2 += p * ar[2]; a3 += p * ar[3];
                a4 += p * ar[4]; a5 += p * ar[5]; a6 += p * ar[6]; a7 += p * ar[7];
            }
            wout[eb * 8 + 0] = a0; wout[eb * 8 + 1] = a1;
            wout[eb * 8 + 2] = a2; wout[eb * 8 + 3] = a3;
            wout[eb * 8 + 4] = a4; wout[eb * 8 + 5] = a5;
            wout[eb * 8 + 6] = a6; wout[eb * 8 + 7] = a7;
        }
    }
}

// ============================================================================
// K5: W_final[b] = W_eff[b] (384x384) @ W_v (384x384), output as bf16 planes.
// fp32 f32x2 GEMM, 128x128 tiles, BK=16. Grid (3,3,4).
// ============================================================================
__global__ void __launch_bounds__(256)
wfinal_kernel(const float* __restrict__ qkv_w)
{
    const int BM = 128, BN = 128, BK = 16;
    __shared__ __align__(16) float As[BK][BM];
    __shared__ __align__(16) float Bs[BK][BN];

    const int b = blockIdx.z;
    const float* A = g_weff + (size_t)b * C_ * C_;
    const float* Bm = qkv_w + (size_t)2 * C_ * C_;   // W_v rows 768..1151
    const int tm = blockIdx.y * BM, tn = blockIdx.x * BN;
    const int tid = threadIdx.x;
    const int tx = tid & 15, ty = tid >> 4;

    u64 acc[8][4];
#pragma unroll
    for (int i = 0; i < 8; i++)
#pragma unroll
        for (int p = 0; p < 4; p++) acc[i][p] = 0ull;

    for (int k0 = 0; k0 < C_; k0 += BK) {
#pragma unroll
        for (int i = 0; i < 2; i++) {
            int f4 = tid + 256 * i;
            int r = f4 >> 2, c4 = (f4 & 3) << 2;
            float4 v = *reinterpret_cast<const float4*>(&A[(size_t)(tm + r) * C_ + k0 + c4]);
            As[c4 + 0][r] = v.x; As[c4 + 1][r] = v.y;
            As[c4 + 2][r] = v.z; As[c4 + 3][r] = v.w;
        }
#pragma unroll
        for (int i = 0; i < 2; i++) {
            int f4 = tid + 256 * i;
            int r = f4 >> 5, c4 = (f4 & 31) << 2;
            *reinterpret_cast<float4*>(&Bs[r][c4]) =
                *reinterpret_cast<const float4*>(&Bm[(size_t)(k0 + r) * C_ + tn + c4]);
        }
        __syncthreads();
#pragma unroll
        for (int kk = 0; kk < BK; kk++) {
            u64 av[8];
#pragma unroll
            for (int i = 0; i < 8; i++) { float a = As[kk][ty * 8 + i]; av[i] = pk2(a, a); }
            u64 bv[4];
            const u64* bp = reinterpret_cast<const u64*>(&Bs[kk][tx * 8]);
#pragma unroll
            for (int p = 0; p < 4; p++) bv[p] = bp[p];
#pragma unroll
            for (int i = 0; i < 8; i++)
#pragma unroll
                for (int p = 0; p < 4; p++)
                    acc[i][p] = fma2(av[i], bv[p], acc[i][p]);
        }
        __syncthreads();
    }

#pragma unroll
    for (int i = 0; i < 8; i++) {
        int row = tm + ty * 8 + i;
        float o[8];
#pragma unroll
        for (int p = 0; p < 4; p++) upk2(acc[i][p], o[2 * p], o[2 * p + 1]);
        uint32_t h0, l0, h1, l1, h2, l2, h3, l3;
        split2(h0, l0, o[0], o[1]);
        split2(h1, l1, o[2], o[3]);
        split2(h2, l2, o[4], o[5]);
        split2(h3, l3, o[6], o[7]);
        size_t ro = ((size_t)b * C_ + row) * (C_ / 2) + ((tn + tx * 8) >> 1);
        *reinterpret_cast<uint4*>(g_wf_hi + ro) = make_uint4(h0, h1, h2, h3);
        *reinterpret_cast<uint4*>(g_wf_lo + ro) = make_uint4(l0, l1, l2, l3);
    }
}

// ===========================================================================
// K6: out[b] = W_final[b] (384x384) @ x[b] (384x16384) + proj_b   (fp32 out)
// Tile 128x256, BK=32, warps 2x4 (64x64), 3-stage cp.async. (validated R7)
// ===========================================================================
#define AH_OFF 0
#define AL_OFF 10240
#define BH_OFF 20480
#define BL_OFF 37376
#define STG_SZ 54272
#define GEMM_SMEM (3 * STG_SZ)

__global__ void __launch_bounds__(256, 1)
gemm_out(const __nv_bfloat16* __restrict__ Ah, const __nv_bfloat16* __restrict__ Al,
         const __nv_bfloat16* __restrict__ Bh, const __nv_bfloat16* __restrict__ Bl,
         int M, int N, int K, long long sA, long long sB,
         float* __restrict__ Of, long long sC, const float* __restrict__ bias)
{
    extern __shared__ char smem[];
    const uint32_t sb = smem_u32(smem);
    const int tid = threadIdx.x;
    const int wid = tid >> 5, lane = tid & 31;

    const int z = blockIdx.z;
    Ah += (size_t)z * sA;  Al += (size_t)z * sA;
    Bh += (size_t)z * sB;  Bl += (size_t)z * sB;
    const int tm = blockIdx.x * 128, tn = blockIdx.y * 256;
    const int warp_m = (wid >> 2) * 64, warp_n = (wid & 3) * 64;

    float acc[4][8][4];
#pragma unroll
    for (int i = 0; i < 4; i++)
#pragma unroll
        for (int j = 0; j < 8; j++)
#pragma unroll
            for (int p = 0; p < 4; p++) acc[i][j][p] = 0.0f;

    auto ISSUE = [&](int s, int c) {
        const int k0 = c * 32;
        const uint32_t stg = sb + s * STG_SZ;
#pragma unroll
        for (int i = 0; i < 4; i++) {
            int id = tid + 256 * i;
            int pl = id >> 9, rem = id & 511, row = rem >> 2, ch = rem & 3;
            const __nv_bfloat16* src = (pl ? Al : Ah) + (size_t)(tm + row) * K + k0 + ch * 8;
            cpa16(stg + AH_OFF + pl * (AL_OFF - AH_OFF) + (uint32_t)((row * 40 + ch * 8) << 1), src);
        }
#pragma unroll
        for (int i = 0; i < 8; i++) {
            int id = tid + 256 * i;
            int pl = id >> 10, rem = id & 1023, row = rem >> 5, ch = rem & 31;
            const __nv_bfloat16* src = (pl ? Bl : Bh) + (size_t)(k0 + row) * N + tn + ch * 8;
            cpa16(stg + BH_OFF + pl * (BL_OFF - BH_OFF) + (uint32_t)((row * 264 + ch * 8) << 1), src);
        }
        CPA_COMMIT();
    };

    auto MMASTEP = [&](int s, int ks) {
        const uint32_t stg = sb + s * STG_SZ;
        uint32_t bh[8][2], bl[8][2];
        {
            uint32_t krow = (uint32_t)(ks * 16 + (lane & 7) + (((lane >> 3) & 1) << 3));
            uint32_t ncol = (uint32_t)(warp_n + ((lane >> 4) << 3));
            uint32_t bd  = stg + BH_OFF + ((krow * 264 + ncol) << 1);
            uint32_t bdl = bd + (BL_OFF - BH_OFF);
            uint32_t r4[4];
#pragma unroll
            for (int j = 0; j < 4; j++) {
                ldsm4t(r4, bd + j * 32);
                bh[2 * j][0] = r4[0]; bh[2 * j][1] = r4[1];
                bh[2 * j + 1][0] = r4[2]; bh[2 * j + 1][1] = r4[3];
            }
#pragma unroll
            for (int j = 0; j < 4; j++) {
                ldsm4t(r4, bdl + j * 32);
                bl[2 * j][0] = r4[0]; bl[2 * j][1] = r4[1];
                bl[2 * j + 1][0] = r4[2]; bl[2 * j + 1][1] = r4[3];
            }
        }
        const uint32_t arow = (uint32_t)(warp_m + (lane & 15));
        const uint32_t akoff = (uint32_t)(ks * 16 + ((lane >> 4) << 3));
#pragma unroll
        for (int mf = 0; mf < 4; mf++) {
            uint32_t ah[4], al[4];
            uint32_t ad = stg + AH_OFF + (((arow + mf * 16) * 40 + akoff) << 1);
            ldsm4(ah, ad);
            ldsm4(al, ad + (AL_OFF - AH_OFF));
#pragma unroll
            for (int nf = 0; nf < 8; nf++) {
                mma16816(acc[mf][nf], ah, bh[nf]);
                mma16816(acc[mf][nf], ah, bl[nf]);
                mma16816(acc[mf][nf], al, bh[nf]);
            }
        }
    };

    const int NC = K >> 5;   // 12
    ISSUE(0, 0);
    ISSUE(1, 1);
    for (int c = 0; c < NC; c++) {
        const int s = c % 3;
        if (c == NC - 1) { CPA_WAIT0(); } else { CPA_WAIT1(); }
        __syncthreads();
        if (c + 2 < NC) ISSUE((c + 2) % 3, c + 2);
        MMASTEP(s, 0);
        MMASTEP(s, 1);
    }
    __syncthreads();

    float* cs = reinterpret_cast<float*>(smem);
    const int g = lane >> 2, t2 = (lane & 3) * 2;
#pragma unroll
    for (int mf = 0; mf < 4; mf++)
#pragma unroll
        for (int nf = 0; nf < 8; nf++) {
            int r0 = warp_m + mf * 16 + g;
            int c0 = warp_n + nf * 8 + t2;
            cs[r0 * 260 + c0]           = acc[mf][nf][0];
            cs[r0 * 260 + c0 + 1]       = acc[mf][nf][1];
            cs[(r0 + 8) * 260 + c0]     = acc[mf][nf][2];
            cs[(r0 + 8) * 260 + c0 + 1] = acc[mf][nf][3];
        }
    __syncthreads();

    const int r = tid >> 1, cb = (tid & 1) * 128;
    const float* ip = &cs[r * 260 + cb];
    float* op = Of + (size_t)z * sC + (size_t)(tm + r) * N + tn + cb;
    const float bval = bias[tm + r];
#pragma unroll
    for (int j = 0; j < 32; j++) {
        float4 v = make_float4(ip[4 * j] + bval, ip[4 * j + 1] + bval,
                               ip[4 * j + 2] + bval, ip[4 * j + 3] + bval);
        reinterpret_cast<float4*>(op)[j] = v;
    }
}

// ============================================================================
extern "C" void kernel_launch(void* const* d_in, const int* in_sizes, int n_in,
                              void* d_out, int out_size)
{
    const float* x           = (const float*)d_in[0];
    const float* qkv_w       = (const float*)d_in[1];
    const float* proj_w      = (const float*)d_in[2];
    const float* proj_b      = (const float*)d_in[3];
    const float* temperature = (const float*)d_in[4];
    float* out = (float*)d_out;

    void* p;
    cudaGetSymbolAddress(&p, g_x_hi);  uint32_t* x_hi = (uint32_t*)p;
    cudaGetSymbolAddress(&p, g_x_lo);  uint32_t* x_lo = (uint32_t*)p;
    cudaGetSymbolAddress(&p, g_wf_hi); uint32_t* wf_hi = (uint32_t*)p;
    cudaGetSymbolAddress(&p, g_wf_lo); uint32_t* wf_lo = (uint32_t*)p;

    cudaFuncSetAttribute((const void*)x2_cp,
                         cudaFuncAttributeMaxDynamicSharedMemorySize, X2_SMEM);
    cudaFuncSetAttribute((const void*)tB_kernel,
                         cudaFuncAttributeMaxDynamicSharedMemorySize, TB_SMEM);
    cudaFuncSetAttribute((const void*)gemm_out,
                         cudaFuncAttributeMaxDynamicSharedMemorySize, GEMM_SMEM);

    // K0: x -> bf16 hi/lo planes
    split_planes<<<2048, 256>>>((const float2*)x, x_hi, x_lo, B_ * C_ * HW_ / 2);

    // K1: X2 upper-block partials (Gram of x)
    x2_cp<<<dim3(6 * NS2, B_), 256, X2_SMEM>>>(
        (const __nv_bfloat16*)x_hi, (const __nv_bfloat16*)x_lo);

    // K2: reduce + mirror
    x2_reduce<<<B_ * C_ * C_ / 256, 256>>>();

    // K3: T = Wqk_h @ X2
    tA_kernel<<<dim3(8, B_ * NH_), 256>>>(qkv_w);

    // K4: Gram->softmax->W_eff fold
    tB_kernel<<<B_ * NH_, 256, TB_SMEM>>>(temperature, proj_w, qkv_w);

    // K5: W_final = W_eff @ W_v  -> bf16 planes
    wfinal_kernel<<<dim3(3, 3, B_), 256>>>(qkv_w);

    // K6: out = W_final @ x + proj_b
    gemm_out<<<dim3(C_ / 128, HW_ / 256, B_), 256, GEMM_SMEM>>>(
        (const __nv_bfloat16*)wf_hi, (const __nv_bfloat16*)wf_lo,
        (const __nv_bfloat16*)x_hi, (const __nv_bfloat16*)x_lo,
        C_, HW_, C_, (long long)C_ * C_, (long long)C_ * HW_,
        out, (long long)C_ * HW_, proj_b);
}

// round 10
// speedup vs baseline: 1.5171x; 1.0179x over previous
#include <cuda_runtime.h>
#include <cuda_bf16.h>
#include <cstdint>

#define B_    4
#define C_    384
#define HW_   16384
#define NH_   8
#define HD_   48
#define NS2   16            // split-K for X2
#define XK_   (HW_ / NS2)   // 1024

typedef unsigned long long u64;

// ---------------------------------------------------------------------------
// Scratch (device globals — no allocation allowed)
// ---------------------------------------------------------------------------
__device__ uint32_t g_x_hi[(size_t)B_ * C_ * HW_ / 2];     // x as bf16 hi plane
__device__ uint32_t g_x_lo[(size_t)B_ * C_ * HW_ / 2];     // x residual plane
__device__ float    g_x2p[(size_t)NS2 * B_ * 6 * 128 * 128]; // X2 partials (upper blocks)
__device__ float    g_x2[(size_t)B_ * C_ * C_];            // X2 full (mirrored)
__device__ float    g_T[(size_t)B_ * 768 * C_];            // T_all = qkv_w[0:768] · X2
__device__ float    g_weff[(size_t)B_ * C_ * C_];          // P with attn folded
__device__ uint32_t g_wf_hi[(size_t)B_ * C_ * C_ / 2];     // W_final hi plane
__device__ uint32_t g_wf_lo[(size_t)B_ * C_ * C_ / 2];     // W_final lo plane

// ---------------------------------------------------------------------------
// Helpers
// ---------------------------------------------------------------------------
__device__ __forceinline__ uint32_t smem_u32(const void* p) {
    uint32_t a;
    asm("{ .reg .u64 t; cvta.to.shared.u64 t, %1; cvt.u32.u64 %0, t; }" : "=r"(a) : "l"(p));
    return a;
}
// fp32 pair -> bf16x2 hi (exact truncation) and bf16x2 lo (rounded residual)
__device__ __forceinline__ void split2(uint32_t& hi, uint32_t& lo, float f0, float f1) {
    uint32_t u0 = __float_as_uint(f0), u1 = __float_as_uint(f1);
    asm("prmt.b32 %0, %1, %2, 0x7632;" : "=r"(hi) : "r"(u0), "r"(u1));
    float h0 = __uint_as_float(u0 & 0xFFFF0000u);
    float h1 = __uint_as_float(u1 & 0xFFFF0000u);
    float l0 = f0 - h0, l1 = f1 - h1;
    asm("cvt.rn.bf16x2.f32 %0, %1, %2;" : "=r"(lo) : "f"(l1), "f"(l0));
}
__device__ __forceinline__ void ldsm4(uint32_t* r, uint32_t addr) {
    asm volatile("ldmatrix.sync.aligned.m8n8.x4.shared.b16 {%0,%1,%2,%3}, [%4];"
                 : "=r"(r[0]), "=r"(r[1]), "=r"(r[2]), "=r"(r[3]) : "r"(addr));
}
__device__ __forceinline__ void ldsm4t(uint32_t* r, uint32_t addr) {
    asm volatile("ldmatrix.sync.aligned.m8n8.x4.trans.shared.b16 {%0,%1,%2,%3}, [%4];"
                 : "=r"(r[0]), "=r"(r[1]), "=r"(r[2]), "=r"(r[3]) : "r"(addr));
}
__device__ __forceinline__ void mma16816(float* d, const uint32_t* a, const uint32_t* b) {
    asm volatile(
        "mma.sync.aligned.m16n8k16.row.col.f32.bf16.bf16.f32 "
        "{%0,%1,%2,%3}, {%4,%5,%6,%7}, {%8,%9}, {%0,%1,%2,%3};"
        : "+f"(d[0]), "+f"(d[1]), "+f"(d[2]), "+f"(d[3])
        : "r"(a[0]), "r"(a[1]), "r"(a[2]), "r"(a[3]), "r"(b[0]), "r"(b[1]));
}
__device__ __forceinline__ void cpa16(uint32_t dst, const void* src) {
    asm volatile("cp.async.cg.shared.global [%0], [%1], 16;" :: "r"(dst), "l"(src) : "memory");
}
#define CPA_COMMIT() asm volatile("cp.async.commit_group;" ::: "memory")
#define CPA_WAIT2()  asm volatile("cp.async.wait_group 2;"  ::: "memory")
#define CPA_WAIT1()  asm volatile("cp.async.wait_group 1;"  ::: "memory")
#define CPA_WAIT0()  asm volatile("cp.async.wait_group 0;"  ::: "memory")

// packed f32x2 for the small fp32 GEMMs
__device__ __forceinline__ u64 pk2(float lo, float hi) {
    u64 r; asm("mov.b64 %0, {%1,%2};" : "=l"(r) : "f"(lo), "f"(hi)); return r;
}
__device__ __forceinline__ void upk2(u64 v, float& lo, float& hi) {
    asm("mov.b64 {%0,%1}, %2;" : "=f"(lo), "=f"(hi) : "l"(v));
}
__device__ __forceinline__ u64 fma2(u64 a, u64 b, u64 c) {
    u64 d; asm("fma.rn.f32x2 %0, %1, %2, %3;" : "=l"(d) : "l"(a), "l"(b), "l"(c)); return d;
}

// ============================================================================
// K0: fp32 -> bf16 hi/lo planes
// ============================================================================
__global__ void __launch_bounds__(256)
split_planes(const float2* __restrict__ src, uint32_t* __restrict__ hp,
             uint32_t* __restrict__ lp, int n)
{
    for (int i = blockIdx.x * blockDim.x + threadIdx.x; i < n; i += gridDim.x * blockDim.x) {
        float2 v = src[i];
        uint32_t h, l;
        split2(h, l, v.x, v.y);
        hp[i] = h; lp[i] = l;
    }
}

// ============================================================================
// K1: X2 partials. Per (b, upper-block-pair, split): P = Xa · Xb^T over XK_.
// Block tile 128x128, warps 2x4 (64x32), BK=64, 3-stage cp.async.
// ============================================================================
#define XT 18432
#define XSTG (4 * XT)
#define X2_SMEM (3 * XSTG)   // 221184

__constant__ int c_BI[6] = {0, 0, 0, 1, 1, 2};
__constant__ int c_BJ[6] = {0, 1, 2, 1, 2, 2};

__global__ void __launch_bounds__(256, 1)
x2_cp(const __nv_bfloat16* __restrict__ Xh, const __nv_bfloat16* __restrict__ Xl)
{
    extern __shared__ char smem[];
    const uint32_t sb = smem_u32(smem);
    const int tid = threadIdx.x;
    const int wid = tid >> 5, lane = tid & 31;
    const int bp = blockIdx.x / NS2, split = blockIdx.x % NS2;
    const int b = blockIdx.y;
    const int bi = c_BI[bp], bj = c_BJ[bp];
    const size_t xbase = (size_t)b * C_ * HW_;
    const int k0base = split * XK_;
    const int warp_m = (wid >> 2) * 64, warp_n = (wid & 3) * 32;

    float acc[4][4][4];
#pragma unroll
    for (int i = 0; i < 4; i++)
#pragma unroll
        for (int j = 0; j < 4; j++)
#pragma unroll
            for (int p = 0; p < 4; p++) acc[i][j][p] = 0.0f;

    auto ISSUE = [&](int s, int c) {
        const int k0 = k0base + c * 64;
        const uint32_t stg = sb + s * XSTG;
#pragma unroll
        for (int i = 0; i < 16; i++) {
            int id = tid + 256 * i;                // 0..4095
            int pt = id >> 10;                     // 0:A_hi 1:A_lo 2:B_hi 3:B_lo
            int rem = id & 1023;
            int row = rem >> 3, ch = rem & 7;
            int chan = ((pt < 2) ? bi : bj) * 128 + row;
            const __nv_bfloat16* src =
                ((pt & 1) ? Xl : Xh) + xbase + (size_t)chan * HW_ + k0 + ch * 8;
            cpa16(stg + pt * XT + (uint32_t)((row * 72 + ch * 8) << 1), src);
        }
        CPA_COMMIT();
    };

    auto MMASTEP = [&](int s, int ks) {
        const uint32_t stg = sb + s * XSTG;
        const uint32_t koff = (uint32_t)(ks * 16 + ((lane >> 4) << 3));
        uint32_t bh[4][2], bl[4][2];
        {
            uint32_t bd = stg + 2 * XT + (((uint32_t)(warp_n + (lane & 15)) * 72 + koff) << 1);
            uint32_t r4[4];
            ldsm4(r4, bd);
            bh[0][0] = r4[0]; bh[0][1] = r4[2]; bh[1][0] = r4[1]; bh[1][1] = r4[3];
            ldsm4(r4, bd + (72 * 16 << 1));   // rows +16
            bh[2][0] = r4[0]; bh[2][1] = r4[2]; bh[3][0] = r4[1]; bh[3][1] = r4[3];
            uint32_t bdl = bd + XT;
            ldsm4(r4, bdl);
            bl[0][0] = r4[0]; bl[0][1] = r4[2]; bl[1][0] = r4[1]; bl[1][1] = r4[3];
            ldsm4(r4, bdl + (72 * 16 << 1));
            bl[2][0] = r4[0]; bl[2][1] = r4[2]; bl[3][0] = r4[1]; bl[3][1] = r4[3];
        }
#pragma unroll
        for (int mf = 0; mf < 4; mf++) {
            uint32_t ah[4], al[4];
            uint32_t ad = stg + (((uint32_t)(warp_m + mf * 16 + (lane & 15)) * 72 + koff) << 1);
            ldsm4(ah, ad);
            ldsm4(al, ad + XT);
#pragma unroll
            for (int nf = 0; nf < 4; nf++) {
                mma16816(acc[mf][nf], ah, bh[nf]);
                mma16816(acc[mf][nf], ah, bl[nf]);
                mma16816(acc[mf][nf], al, bh[nf]);
            }
        }
    };

    const int NC = XK_ >> 6;   // 16
    ISSUE(0, 0);
    ISSUE(1, 1);
    for (int c = 0; c < NC; c++) {
        const int s = c % 3;
        if (c == NC - 1) { CPA_WAIT0(); } else { CPA_WAIT1(); }
        __syncthreads();
        if (c + 2 < NC) ISSUE((c + 2) % 3, c + 2);
        MMASTEP(s, 0); MMASTEP(s, 1); MMASTEP(s, 2); MMASTEP(s, 3);
    }

    float* pb = g_x2p + ((size_t)(b * NS2 + split) * 6 + bp) * 16384;
    const int g = lane >> 2, t2 = (lane & 3) * 2;
#pragma unroll
    for (int mf = 0; mf < 4; mf++)
#pragma unroll
        for (int nf = 0; nf < 4; nf++) {
            int r0 = warp_m + mf * 16 + g;
            int c0 = warp_n + nf * 8 + t2;
            pb[r0 * 128 + c0]           = acc[mf][nf][0];
            pb[r0 * 128 + c0 + 1]       = acc[mf][nf][1];
            pb[(r0 + 8) * 128 + c0]     = acc[mf][nf][2];
            pb[(r0 + 8) * 128 + c0 + 1] = acc[mf][nf][3];
        }
}

// ============================================================================
// K2: reduce split-K partials into full mirrored X2 [b][384][384]
// ============================================================================
__global__ void __launch_bounds__(256)
x2_reduce()
{
    int idx = blockIdx.x * 256 + threadIdx.x;          // 0 .. 4*384*384-1
    int b = idx / (C_ * C_);
    int rem = idx % (C_ * C_);
    int i = rem / C_, j = rem % C_;
    int bi = i >> 7, bj = j >> 7;
    int li, lj;
    int bp;
    if (bi <= bj) { bp = bi * 3 - bi * (bi - 1) / 2 + (bj - bi); li = i & 127; lj = j & 127; }
    else          { bp = bj * 3 - bj * (bj - 1) / 2 + (bi - bj); li = j & 127; lj = i & 127; }
    float s = 0.0f;
#pragma unroll
    for (int sp = 0; sp < NS2; sp++)
        s += g_x2p[((size_t)(b * NS2 + sp) * 6 + bp) * 16384 + li * 128 + lj];
    g_x2[idx] = s;
}

// ============================================================================
// K3: T_all[b] (768x384) = qkv_w[0:768] @ X2[b].  f32x2 GEMM.
// Tile 64x128, BK=16, 256 threads, 4x8 per thread. Grid (3, 12, 4) = 144.
// ============================================================================
__global__ void __launch_bounds__(256)
tA_gemm(const float* __restrict__ qkv_w)
{
    const int BK = 16;
    __shared__ __align__(16) float As[BK][68];
    __shared__ __align__(16) float Bs[BK][132];

    const int b = blockIdx.z;
    const float* Bm = g_x2 + (size_t)b * C_ * C_;
    const int tm = blockIdx.y * 64, tn = blockIdx.x * 128;
    const int tid = threadIdx.x;
    const int tx = tid & 15, ty = tid >> 4;

    u64 acc[4][4];
#pragma unroll
    for (int i = 0; i < 4; i++)
#pragma unroll
        for (int p = 0; p < 4; p++) acc[i][p] = 0ull;

    for (int k0 = 0; k0 < C_; k0 += BK) {
        {   // A tile 64x16 = 256 float4, transposed store
            int r = tid >> 2, c4 = (tid & 3) << 2;
            float4 v = *reinterpret_cast<const float4*>(&qkv_w[(size_t)(tm + r) * C_ + k0 + c4]);
            As[c4 + 0][r] = v.x; As[c4 + 1][r] = v.y;
            As[c4 + 2][r] = v.z; As[c4 + 3][r] = v.w;
        }
#pragma unroll
        for (int i = 0; i < 2; i++) {   // B tile 16x128 = 512 float4
            int f4 = tid + 256 * i;
            int r = f4 >> 5, c4 = (f4 & 31) << 2;
            *reinterpret_cast<float4*>(&Bs[r][c4]) =
                *reinterpret_cast<const float4*>(&Bm[(size_t)(k0 + r) * C_ + tn + c4]);
        }
        __syncthreads();
#pragma unroll
        for (int kk = 0; kk < BK; kk++) {
            u64 av[4];
#pragma unroll
            for (int i = 0; i < 4; i++) { float a = As[kk][ty * 4 + i]; av[i] = pk2(a, a); }
            u64 bv[4];
            const u64* bp = reinterpret_cast<const u64*>(&Bs[kk][tx * 8]);
#pragma unroll
            for (int p = 0; p < 4; p++) bv[p] = bp[p];
#pragma unroll
            for (int i = 0; i < 4; i++)
#pragma unroll
                for (int p = 0; p < 4; p++)
                    acc[i][p] = fma2(av[i], bv[p], acc[i][p]);
        }
        __syncthreads();
    }

    float* T = g_T + (size_t)b * 768 * C_;
#pragma unroll
    for (int i = 0; i < 4; i++) {
        int row = tm + ty * 4 + i;
        float o[8];
#pragma unroll
        for (int p = 0; p < 4; p++) upk2(acc[i][p], o[2 * p], o[2 * p + 1]);
        float4* op = reinterpret_cast<float4*>(&T[(size_t)row * C_ + tn + tx * 8]);
        op[0] = make_float4(o[0], o[1], o[2], o[3]);
        op[1] = make_float4(o[4], o[5], o[6], o[7]);
    }
}

// ============================================================================
// K4: per (b,h): Gqk + norms from T_all, softmax, fold attn into proj_w slice.
// T_all layout: rows 0..383 = q rows (all heads), 384..767 = k rows.
// smem (floats): sWk[48*385] | sG[2304] | sInv[96] | sAttn[2304] | spw[384*49]
// ============================================================================
#define TB_OWK  0
#define TB_OG   18480
#define TB_OINV 20784
#define TB_OATT 20880
#define TB_OPW  23184
#define TB_SMEM ((TB_OPW + 384 * 49) * 4)   // 168000 B

__global__ void __launch_bounds__(256)
tB_kernel(const float* __restrict__ temperature,
          const float* __restrict__ proj_w,
          const float* __restrict__ qkv_w)
{
    extern __shared__ float sm[];
    float* sWk   = sm + TB_OWK;
    float* sG    = sm + TB_OG;
    float* sInv  = sm + TB_OINV;
    float* sAttn = sm + TB_OATT;
    float* spw   = sm + TB_OPW;

    const int bh = blockIdx.x;
    const int b = bh >> 3, h = bh & 7;
    const int tid = threadIdx.x;
    const float* Tq = g_T + (size_t)b * 768 * C_ + (size_t)h * HD_ * C_;
    const float* Tk = g_T + (size_t)b * 768 * C_ + (size_t)(C_ + h * HD_) * C_;

    // load Wk rows (k-side of the head) and proj_w slice
    for (int idx = tid; idx < 48 * C_; idx += 256) {
        int e = idx / C_, k = idx % C_;
        sWk[e * 385 + k] = qkv_w[(size_t)(C_ + h * HD_ + e) * C_ + k];
    }
    for (int idx = tid; idx < 384 * 12; idx += 256) {
        int o = idx / 12, d4 = (idx % 12) * 4;
        float4 v = *reinterpret_cast<const float4*>(&proj_w[(size_t)o * C_ + h * 48 + d4]);
        float* dst = &spw[o * 49 + d4];
        dst[0] = v.x; dst[1] = v.y; dst[2] = v.z; dst[3] = v.w;
    }
    __syncthreads();

    // Gqk[d][e] = Tq[d] . Wk[e]
    for (int idx = tid; idx < 48 * 48; idx += 256) {
        int d = idx / 48, e = idx % 48;
        const float* tr = &Tq[(size_t)d * C_];
        const float* wr = &sWk[e * 385];
        float s = 0.0f;
#pragma unroll 8
        for (int k = 0; k < C_; k++) s += tr[k] * wr[k];
        sG[idx] = s;
    }
    // norms: q: Tq[d].Wq[d]   k: Tk[e].Wk[e]
    if (tid < 96) {
        float s = 0.0f;
        if (tid < 48) {
            const float* tr = &Tq[(size_t)tid * C_];
            const float* wq = &qkv_w[(size_t)(h * HD_ + tid) * C_];
#pragma unroll 8
            for (int k = 0; k < C_; k++) s += tr[k] * wq[k];
        } else {
            int e = tid - 48;
            const float* tr = &Tk[(size_t)e * C_];
            const float* wr = &sWk[e * 385];
#pragma unroll 8
            for (int k = 0; k < C_; k++) s += tr[k] * wr[k];
        }
        sInv[tid] = 1.0f / fmaxf(sqrtf(s), 1e-12f);
    }
    __syncthreads();

    const float temp = temperature[h];
    if (tid < 48) {
        int d = tid;
        float l[48];
        float mx = -1e30f;
#pragma unroll
        for (int e = 0; e < 48; e++) {
            float v = sG[d * 48 + e] * sInv[d] * sInv[48 + e] * temp;
            l[e] = v;
            mx = fmaxf(mx, v);
        }
        float sum = 0.0f;
#pragma unroll
        for (int e = 0; e < 48; e++) { l[e] = expf(l[e] - mx); sum += l[e]; }
        float inv = 1.0f / sum;
#pragma unroll
        for (int e = 0; e < 48; e++) sAttn[d * 48 + e] = l[e] * inv;
    }
    __syncthreads();

    // W_eff[o][h*48+e] = sum_d proj_w[o][h*48+d] * attn[d][e]
    for (int o = tid; o < 384; o += 256) {
        const float* pw = &spw[o * 49];
        float* wout = &g_weff[((size_t)b * C_ + o) * C_ + h * 48];
#pragma unroll
        for (int eb = 0; eb < 6; eb++) {
            float a0 = 0, a1 = 0, a2 = 0, a3 = 0, a4 = 0, a5 = 0, a6 = 0, a7 = 0;
#pragma unroll 8
            for (int d = 0; d < 48; d++) {
                float p = pw[d];
                const float* ar = &sAttn[d * 48 + eb * 8];
                a0 += p * ar[0]; a1 += p * ar[1]; a2 += p * ar[2]; a3 += p * ar[3];
                a4 += p * ar[4]; a5 += p * ar[5]; a6 += p * ar[6]; a7 += p * ar[7];
            }
            wout[eb * 8 + 0] = a0; wout[eb * 8 + 1] = a1;
            wout[eb * 8 + 2] = a2; wout[eb * 8 + 3] = a3;
            wout[eb * 8 + 4] = a4; wout[eb * 8 + 5] = a5;
            wout[eb * 8 + 6] = a6; wout[eb * 8 + 7] = a7;
        }
    }
}

// ============================================================================
// K5: W_final[b] = W_eff[b] (384x384) @ W_v (384x384), output as bf16 planes.
// fp32 f32x2 GEMM, 128x128 tiles, BK=16. Grid (3,3,4).
// ============================================================================
__global__ void __launch_bounds__(256)
wfinal_kernel(const float* __restrict__ qkv_w)
{
    const int BM = 128, BN = 128, BK = 16;
    __shared__ __align__(16) float As[BK][BM];
    __shared__ __align__(16) float Bs[BK][BN];

    const int b = blockIdx.z;
    const float* A = g_weff + (size_t)b * C_ * C_;
    const float* Bm = qkv_w + (size_t)2 * C_ * C_;   // W_v rows 768..1151
    const int tm = blockIdx.y * BM, tn = blockIdx.x * BN;
    const int tid = threadIdx.x;
    const int tx = tid & 15, ty = tid >> 4;

    u64 acc[8][4];
#pragma unroll
    for (int i = 0; i < 8; i++)
#pragma unroll
        for (int p = 0; p < 4; p++) acc[i][p] = 0ull;

    for (int k0 = 0; k0 < C_; k0 += BK) {
#pragma unroll
        for (int i = 0; i < 2; i++) {
            int f4 = tid + 256 * i;
            int r = f4 >> 2, c4 = (f4 & 3) << 2;
            float4 v = *reinterpret_cast<const float4*>(&A[(size_t)(tm + r) * C_ + k0 + c4]);
            As[c4 + 0][r] = v.x; As[c4 + 1][r] = v.y;
            As[c4 + 2][r] = v.z; As[c4 + 3][r] = v.w;
        }
#pragma unroll
        for (int i = 0; i < 2; i++) {
            int f4 = tid + 256 * i;
            int r = f4 >> 5, c4 = (f4 & 31) << 2;
            *reinterpret_cast<float4*>(&Bs[r][c4]) =
                *reinterpret_cast<const float4*>(&Bm[(size_t)(k0 + r) * C_ + tn + c4]);
        }
        __syncthreads();
#pragma unroll
        for (int kk = 0; kk < BK; kk++) {
            u64 av[8];
#pragma unroll
            for (int i = 0; i < 8; i++) { float a = As[kk][ty * 8 + i]; av[i] = pk2(a, a); }
            u64 bv[4];
            const u64* bp = reinterpret_cast<const u64*>(&Bs[kk][tx * 8]);
#pragma unroll
            for (int p = 0; p < 4; p++) bv[p] = bp[p];
#pragma unroll
            for (int i = 0; i < 8; i++)
#pragma unroll
                for (int p = 0; p < 4; p++)
                    acc[i][p] = fma2(av[i], bv[p], acc[i][p]);
        }
        __syncthreads();
    }

#pragma unroll
    for (int i = 0; i < 8; i++) {
        int row = tm + ty * 8 + i;
        float o[8];
#pragma unroll
        for (int p = 0; p < 4; p++) upk2(acc[i][p], o[2 * p], o[2 * p + 1]);
        uint32_t h0, l0, h1, l1, h2, l2, h3, l3;
        split2(h0, l0, o[0], o[1]);
        split2(h1, l1, o[2], o[3]);
        split2(h2, l2, o[4], o[5]);
        split2(h3, l3, o[6], o[7]);
        size_t ro = ((size_t)b * C_ + row) * (C_ / 2) + ((tn + tx * 8) >> 1);
        *reinterpret_cast<uint4*>(g_wf_hi + ro) = make_uint4(h0, h1, h2, h3);
        *reinterpret_cast<uint4*>(g_wf_lo + ro) = make_uint4(l0, l1, l2, l3);
    }
}

// ===========================================================================
// K6: out[b] = W_final[b] (384x384) @ x[b] (384x16384) + proj_b   (fp32 out)
// Tile 128x256, BK=32, warps 2x4 (64x64), 4-stage cp.async.
// ===========================================================================
#define AH_OFF 0
#define AL_OFF 10240
#define BH_OFF 20480
#define BL_OFF 37376
#define STG_SZ 54272
#define GEMM_SMEM (4 * STG_SZ)   // 217088

__global__ void __launch_bounds__(256, 1)
gemm_out(const __nv_bfloat16* __restrict__ Ah, const __nv_bfloat16* __restrict__ Al,
         const __nv_bfloat16* __restrict__ Bh, const __nv_bfloat16* __restrict__ Bl,
         int M, int N, int K, long long sA, long long sB,
         float* __restrict__ Of, long long sC, const float* __restrict__ bias)
{
    extern __shared__ char smem[];
    const uint32_t sb = smem_u32(smem);
    const int tid = threadIdx.x;
    const int wid = tid >> 5, lane = tid & 31;

    const int z = blockIdx.z;
    Ah += (size_t)z * sA;  Al += (size_t)z * sA;
    Bh += (size_t)z * sB;  Bl += (size_t)z * sB;
    const int tm = blockIdx.x * 128, tn = blockIdx.y * 256;
    const int warp_m = (wid >> 2) * 64, warp_n = (wid & 3) * 64;

    float acc[4][8][4];
#pragma unroll
    for (int i = 0; i < 4; i++)
#pragma unroll
        for (int j = 0; j < 8; j++)
#pragma unroll
            for (int p = 0; p < 4; p++) acc[i][j][p] = 0.0f;

    auto ISSUE = [&](int s, int c) {
        const int k0 = c * 32;
        const uint32_t stg = sb + s * STG_SZ;
#pragma unroll
        for (int i = 0; i < 4; i++) {
            int id = tid + 256 * i;
            int pl = id >> 9, rem = id & 511, row = rem >> 2, ch = rem & 3;
            const __nv_bfloat16* src = (pl ? Al : Ah) + (size_t)(tm + row) * K + k0 + ch * 8;
            cpa16(stg + AH_OFF + pl * (AL_OFF - AH_OFF) + (uint32_t)((row * 40 + ch * 8) << 1), src);
        }
#pragma unroll
        for (int i = 0; i < 8; i++) {
            int id = tid + 256 * i;
            int pl = id >> 10, rem = id & 1023, row = rem >> 5, ch = rem & 31;
            const __nv_bfloat16* src = (pl ? Bl : Bh) + (size_t)(k0 + row) * N + tn + ch * 8;
            cpa16(stg + BH_OFF + pl * (BL_OFF - BH_OFF) + (uint32_t)((row * 264 + ch * 8) << 1), src);
        }
        CPA_COMMIT();
    };

    auto MMASTEP = [&](int s, int ks) {
        const uint32_t stg = sb + s * STG_SZ;
        uint32_t bh[8][2], bl[8][2];
        {
            uint32_t krow = (uint32_t)(ks * 16 + (lane & 7) + (((lane >> 3) & 1) << 3));
            uint32_t ncol = (uint32_t)(warp_n + ((lane >> 4) << 3));
            uint32_t bd  = stg + BH_OFF + ((krow * 264 + ncol) << 1);
            uint32_t bdl = bd + (BL_OFF - BH_OFF);
            uint32_t r4[4];
#pragma unroll
            for (int j = 0; j < 4; j++) {
                ldsm4t(r4, bd + j * 32);
                bh[2 * j][0] = r4[0]; bh[2 * j][1] = r4[1];
                bh[2 * j + 1][0] = r4[2]; bh[2 * j + 1][1] = r4[3];
            }
#pragma unroll
            for (int j = 0; j < 4; j++) {
                ldsm4t(r4, bdl + j * 32);
                bl[2 * j][0] = r4[0]; bl[2 * j][1] = r4[1];
                bl[2 * j + 1][0] = r4[2]; bl[2 * j + 1][1] = r4[3];
            }
        }
        const uint32_t arow = (uint32_t)(warp_m + (lane & 15));
        const uint32_t akoff = (uint32_t)(ks * 16 + ((lane >> 4) << 3));
#pragma unroll
        for (int mf = 0; mf < 4; mf++) {
            uint32_t ah[4], al[4];
            uint32_t ad = stg + AH_OFF + (((arow + mf * 16) * 40 + akoff) << 1);
            ldsm4(ah, ad);
            ldsm4(al, ad + (AL_OFF - AH_OFF));
#pragma unroll
            for (int nf = 0; nf < 8; nf++) {
                mma16816(acc[mf][nf], ah, bh[nf]);
                mma16816(acc[mf][nf], ah, bl[nf]);
                mma16816(acc[mf][nf], al, bh[nf]);
            }
        }
    };

    const int NC = K >> 5;   // 12
    ISSUE(0, 0);
    ISSUE(1, 1);
    ISSUE(2, 2);
    for (int c = 0; c < NC; c++) {
        const int s = c & 3;
        const int left = NC - c;
        if (left >= 3) { CPA_WAIT2(); } else if (left == 2) { CPA_WAIT1(); } else { CPA_WAIT0(); }
        __syncthreads();
        if (c + 3 < NC) ISSUE((c + 3) & 3, c + 3);
        MMASTEP(s, 0);
        MMASTEP(s, 1);
    }
    __syncthreads();

    float* cs = reinterpret_cast<float*>(smem);
    const int g = lane >> 2, t2 = (lane & 3) * 2;
#pragma unroll
    for (int mf = 0; mf < 4; mf++)
#pragma unroll
        for (int nf = 0; nf < 8; nf++) {
            int r0 = warp_m + mf * 16 + g;
            int c0 = warp_n + nf * 8 + t2;
            cs[r0 * 260 + c0]           = acc[mf][nf][0];
            cs[r0 * 260 + c0 + 1]       = acc[mf][nf][1];
            cs[(r0 + 8) * 260 + c0]     = acc[mf][nf][2];
            cs[(r0 + 8) * 260 + c0 + 1] = acc[mf][nf][3];
        }
    __syncthreads();

    const int r = tid >> 1, cb = (tid & 1) * 128;
    const float* ip = &cs[r * 260 + cb];
    float* op = Of + (size_t)z * sC + (size_t)(tm + r) * N + tn + cb;
    const float bval = bias[tm + r];
#pragma unroll
    for (int j = 0; j < 32; j++) {
        float4 v = make_float4(ip[4 * j] + bval, ip[4 * j + 1] + bval,
                               ip[4 * j + 2] + bval, ip[4 * j + 3] + bval);
        reinterpret_cast<float4*>(op)[j] = v;
    }
}

// ============================================================================
extern "C" void kernel_launch(void* const* d_in, const int* in_sizes, int n_in,
                              void* d_out, int out_size)
{
    const float* x           = (const float*)d_in[0];
    const float* qkv_w       = (const float*)d_in[1];
    const float* proj_w      = (const float*)d_in[2];
    const float* proj_b      = (const float*)d_in[3];
    const float* temperature = (const float*)d_in[4];
    float* out = (float*)d_out;

    void* p;
    cudaGetSymbolAddress(&p, g_x_hi);  uint32_t* x_hi = (uint32_t*)p;
    cudaGetSymbolAddress(&p, g_x_lo);  uint32_t* x_lo = (uint32_t*)p;
    cudaGetSymbolAddress(&p, g_wf_hi); uint32_t* wf_hi = (uint32_t*)p;
    cudaGetSymbolAddress(&p, g_wf_lo); uint32_t* wf_lo = (uint32_t*)p;

    cudaFuncSetAttribute((const void*)x2_cp,
                         cudaFuncAttributeMaxDynamicSharedMemorySize, X2_SMEM);
    cudaFuncSetAttribute((const void*)tB_kernel,
                         cudaFuncAttributeMaxDynamicSharedMemorySize, TB_SMEM);
    cudaFuncSetAttribute((const void*)gemm_out,
                         cudaFuncAttributeMaxDynamicSharedMemorySize, GEMM_SMEM);

    // K0: x -> bf16 hi/lo planes
    split_planes<<<2048, 256>>>((const float2*)x, x_hi, x_lo, B_ * C_ * HW_ / 2);

    // K1: X2 upper-block partials (Gram of x)
    x2_cp<<<dim3(6 * NS2, B_), 256, X2_SMEM>>>(
        (const __nv_bfloat16*)x_hi, (const __nv_bfloat16*)x_lo);

    // K2: reduce + mirror
    x2_reduce<<<B_ * C_ * C_ / 256, 256>>>();

    // K3: T_all = qkv_w[0:768] @ X2  (batched f32x2 GEMM)
    tA_gemm<<<dim3(3, 12, B_), 256>>>(qkv_w);

    // K4: Gram->softmax->W_eff fold
    tB_kernel<<<B_ * NH_, 256, TB_SMEM>>>(temperature, proj_w, qkv_w);

    // K5: W_final = W_eff @ W_v  -> bf16 planes
    wfinal_kernel<<<dim3(3, 3, B_), 256>>>(qkv_w);

    // K6: out = W_final @ x + proj_b
    gemm_out<<<dim3(C_ / 128, HW_ / 256, B_), 256, GEMM_SMEM>>>(
        (const __nv_bfloat16*)wf_hi, (const __nv_bfloat16*)wf_lo,
        (const __nv_bfloat16*)x_hi, (const __nv_bfloat16*)x_lo,
        C_, HW_, C_, (long long)C_ * C_, (long long)C_ * HW_,
        out, (long long)C_ * HW_, proj_b);
}

// round 11
// speedup vs baseline: 1.5173x; 1.0001x over previous
#include <cuda_runtime.h>
#include <cuda_bf16.h>
#include <cstdint>

#define B_    4
#define C_    384
#define HW_   16384
#define NH_   8
#define HD_   48
#define NS2   32            // split-K for X2
#define XK_   (HW_ / NS2)   // 512

typedef unsigned long long u64;

// ---------------------------------------------------------------------------
// Scratch (device globals — no allocation allowed)
// ---------------------------------------------------------------------------
__device__ uint32_t g_x_hi[(size_t)B_ * C_ * HW_ / 2];     // x as bf16 hi plane
__device__ uint32_t g_x_lo[(size_t)B_ * C_ * HW_ / 2];     // x residual plane
__device__ float    g_x2p[(size_t)NS2 * B_ * 6 * 128 * 128]; // X2 partials (upper blocks)
__device__ float    g_x2[(size_t)B_ * C_ * C_];            // X2 full (mirrored)
__device__ float    g_T[(size_t)B_ * 768 * C_];            // T_all = qkv_w[0:768] · X2
__device__ float    g_weff[(size_t)B_ * C_ * C_];          // P with attn folded
__device__ uint32_t g_wf_hi[(size_t)B_ * C_ * C_ / 2];     // W_final hi plane
__device__ uint32_t g_wf_lo[(size_t)B_ * C_ * C_ / 2];     // W_final lo plane

// ---------------------------------------------------------------------------
// Helpers
// ---------------------------------------------------------------------------
__device__ __forceinline__ uint32_t smem_u32(const void* p) {
    uint32_t a;
    asm("{ .reg .u64 t; cvta.to.shared.u64 t, %1; cvt.u32.u64 %0, t; }" : "=r"(a) : "l"(p));
    return a;
}
// fp32 pair -> bf16x2 hi (exact truncation) and bf16x2 lo (rounded residual)
__device__ __forceinline__ void split2(uint32_t& hi, uint32_t& lo, float f0, float f1) {
    uint32_t u0 = __float_as_uint(f0), u1 = __float_as_uint(f1);
    asm("prmt.b32 %0, %1, %2, 0x7632;" : "=r"(hi) : "r"(u0), "r"(u1));
    float h0 = __uint_as_float(u0 & 0xFFFF0000u);
    float h1 = __uint_as_float(u1 & 0xFFFF0000u);
    float l0 = f0 - h0, l1 = f1 - h1;
    asm("cvt.rn.bf16x2.f32 %0, %1, %2;" : "=r"(lo) : "f"(l1), "f"(l0));
}
__device__ __forceinline__ void ldsm4(uint32_t* r, uint32_t addr) {
    asm volatile("ldmatrix.sync.aligned.m8n8.x4.shared.b16 {%0,%1,%2,%3}, [%4];"
                 : "=r"(r[0]), "=r"(r[1]), "=r"(r[2]), "=r"(r[3]) : "r"(addr));
}
__device__ __forceinline__ void ldsm4t(uint32_t* r, uint32_t addr) {
    asm volatile("ldmatrix.sync.aligned.m8n8.x4.trans.shared.b16 {%0,%1,%2,%3}, [%4];"
                 : "=r"(r[0]), "=r"(r[1]), "=r"(r[2]), "=r"(r[3]) : "r"(addr));
}
__device__ __forceinline__ void mma16816(float* d, const uint32_t* a, const uint32_t* b) {
    asm volatile(
        "mma.sync.aligned.m16n8k16.row.col.f32.bf16.bf16.f32 "
        "{%0,%1,%2,%3}, {%4,%5,%6,%7}, {%8,%9}, {%0,%1,%2,%3};"
        : "+f"(d[0]), "+f"(d[1]), "+f"(d[2]), "+f"(d[3])
        : "r"(a[0]), "r"(a[1]), "r"(a[2]), "r"(a[3]), "r"(b[0]), "r"(b[1]));
}
__device__ __forceinline__ void cpa16(uint32_t dst, const void* src) {
    asm volatile("cp.async.cg.shared.global [%0], [%1], 16;" :: "r"(dst), "l"(src) : "memory");
}
#define CPA_COMMIT() asm volatile("cp.async.commit_group;" ::: "memory")
#define CPA_WAIT2()  asm volatile("cp.async.wait_group 2;"  ::: "memory")
#define CPA_WAIT1()  asm volatile("cp.async.wait_group 1;"  ::: "memory")
#define CPA_WAIT0()  asm volatile("cp.async.wait_group 0;"  ::: "memory")

// packed f32x2 for the small fp32 GEMMs
__device__ __forceinline__ u64 pk2(float lo, float hi) {
    u64 r; asm("mov.b64 %0, {%1,%2};" : "=l"(r) : "f"(lo), "f"(hi)); return r;
}
__device__ __forceinline__ void upk2(u64 v, float& lo, float& hi) {
    asm("mov.b64 {%0,%1}, %2;" : "=f"(lo), "=f"(hi) : "l"(v));
}
__device__ __forceinline__ u64 fma2(u64 a, u64 b, u64 c) {
    u64 d; asm("fma.rn.f32x2 %0, %1, %2, %3;" : "=l"(d) : "l"(a), "l"(b), "l"(c)); return d;
}

// ============================================================================
// K0: fp32 -> bf16 hi/lo planes
// ============================================================================
__global__ void __launch_bounds__(256)
split_planes(const float2* __restrict__ src, uint32_t* __restrict__ hp,
             uint32_t* __restrict__ lp, int n)
{
    for (int i = blockIdx.x * blockDim.x + threadIdx.x; i < n; i += gridDim.x * blockDim.x) {
        float2 v = src[i];
        uint32_t h, l;
        split2(h, l, v.x, v.y);
        hp[i] = h; lp[i] = l;
    }
}

// ============================================================================
// K1: X2 partials. Per (b, upper-block-pair, split): P = Xa · Xb^T over XK_.
// Block tile 128x128, warps 2x4 (64x32), BK=64, 3-stage cp.async.
// ============================================================================
#define XT 18432
#define XSTG (4 * XT)
#define X2_SMEM (3 * XSTG)   // 221184

__constant__ int c_BI[6] = {0, 0, 0, 1, 1, 2};
__constant__ int c_BJ[6] = {0, 1, 2, 1, 2, 2};

__global__ void __launch_bounds__(256, 1)
x2_cp(const __nv_bfloat16* __restrict__ Xh, const __nv_bfloat16* __restrict__ Xl)
{
    extern __shared__ char smem[];
    const uint32_t sb = smem_u32(smem);
    const int tid = threadIdx.x;
    const int wid = tid >> 5, lane = tid & 31;
    const int bp = blockIdx.x / NS2, split = blockIdx.x % NS2;
    const int b = blockIdx.y;
    const int bi = c_BI[bp], bj = c_BJ[bp];
    const size_t xbase = (size_t)b * C_ * HW_;
    const int k0base = split * XK_;
    const int warp_m = (wid >> 2) * 64, warp_n = (wid & 3) * 32;

    float acc[4][4][4];
#pragma unroll
    for (int i = 0; i < 4; i++)
#pragma unroll
        for (int j = 0; j < 4; j++)
#pragma unroll
            for (int p = 0; p < 4; p++) acc[i][j][p] = 0.0f;

    auto ISSUE = [&](int s, int c) {
        const int k0 = k0base + c * 64;
        const uint32_t stg = sb + s * XSTG;
#pragma unroll
        for (int i = 0; i < 16; i++) {
            int id = tid + 256 * i;                // 0..4095
            int pt = id >> 10;                     // 0:A_hi 1:A_lo 2:B_hi 3:B_lo
            int rem = id & 1023;
            int row = rem >> 3, ch = rem & 7;
            int chan = ((pt < 2) ? bi : bj) * 128 + row;
            const __nv_bfloat16* src =
                ((pt & 1) ? Xl : Xh) + xbase + (size_t)chan * HW_ + k0 + ch * 8;
            cpa16(stg + pt * XT + (uint32_t)((row * 72 + ch * 8) << 1), src);
        }
        CPA_COMMIT();
    };

    auto MMASTEP = [&](int s, int ks) {
        const uint32_t stg = sb + s * XSTG;
        const uint32_t koff = (uint32_t)(ks * 16 + ((lane >> 4) << 3));
        uint32_t bh[4][2], bl[4][2];
        {
            uint32_t bd = stg + 2 * XT + (((uint32_t)(warp_n + (lane & 15)) * 72 + koff) << 1);
            uint32_t r4[4];
            ldsm4(r4, bd);
            bh[0][0] = r4[0]; bh[0][1] = r4[2]; bh[1][0] = r4[1]; bh[1][1] = r4[3];
            ldsm4(r4, bd + (72 * 16 << 1));   // rows +16
            bh[2][0] = r4[0]; bh[2][1] = r4[2]; bh[3][0] = r4[1]; bh[3][1] = r4[3];
            uint32_t bdl = bd + XT;
            ldsm4(r4, bdl);
            bl[0][0] = r4[0]; bl[0][1] = r4[2]; bl[1][0] = r4[1]; bl[1][1] = r4[3];
            ldsm4(r4, bdl + (72 * 16 << 1));
            bl[2][0] = r4[0]; bl[2][1] = r4[2]; bl[3][0] = r4[1]; bl[3][1] = r4[3];
        }
#pragma unroll
        for (int mf = 0; mf < 4; mf++) {
            uint32_t ah[4], al[4];
            uint32_t ad = stg + (((uint32_t)(warp_m + mf * 16 + (lane & 15)) * 72 + koff) << 1);
            ldsm4(ah, ad);
            ldsm4(al, ad + XT);
#pragma unroll
            for (int nf = 0; nf < 4; nf++) {
                mma16816(acc[mf][nf], ah, bh[nf]);
                mma16816(acc[mf][nf], ah, bl[nf]);
                mma16816(acc[mf][nf], al, bh[nf]);
            }
        }
    };

    const int NC = XK_ >> 6;   // 8
    ISSUE(0, 0);
    ISSUE(1, 1);
    for (int c = 0; c < NC; c++) {
        const int s = c % 3;
        if (c == NC - 1) { CPA_WAIT0(); } else { CPA_WAIT1(); }
        __syncthreads();
        if (c + 2 < NC) ISSUE((c + 2) % 3, c + 2);
        MMASTEP(s, 0); MMASTEP(s, 1); MMASTEP(s, 2); MMASTEP(s, 3);
    }

    float* pb = g_x2p + ((size_t)(b * NS2 + split) * 6 + bp) * 16384;
    const int g = lane >> 2, t2 = (lane & 3) * 2;
#pragma unroll
    for (int mf = 0; mf < 4; mf++)
#pragma unroll
        for (int nf = 0; nf < 4; nf++) {
            int r0 = warp_m + mf * 16 + g;
            int c0 = warp_n + nf * 8 + t2;
            pb[r0 * 128 + c0]           = acc[mf][nf][0];
            pb[r0 * 128 + c0 + 1]       = acc[mf][nf][1];
            pb[(r0 + 8) * 128 + c0]     = acc[mf][nf][2];
            pb[(r0 + 8) * 128 + c0 + 1] = acc[mf][nf][3];
        }
}

// ============================================================================
// K2: reduce split-K partials into full mirrored X2 [b][384][384]
// ============================================================================
__global__ void __launch_bounds__(256)
x2_reduce()
{
    int idx = blockIdx.x * 256 + threadIdx.x;          // 0 .. 4*384*384-1
    int b = idx / (C_ * C_);
    int rem = idx % (C_ * C_);
    int i = rem / C_, j = rem % C_;
    int bi = i >> 7, bj = j >> 7;
    int li, lj;
    int bp;
    if (bi <= bj) { bp = bi * 3 - bi * (bi - 1) / 2 + (bj - bi); li = i & 127; lj = j & 127; }
    else          { bp = bj * 3 - bj * (bj - 1) / 2 + (bi - bj); li = j & 127; lj = i & 127; }
    float s = 0.0f;
#pragma unroll
    for (int sp = 0; sp < NS2; sp++)
        s += g_x2p[((size_t)(b * NS2 + sp) * 6 + bp) * 16384 + li * 128 + lj];
    g_x2[idx] = s;
}

// ============================================================================
// K3: T_all[b] (768x384) = qkv_w[0:768] @ X2[b].  f32x2 GEMM.
// Tile 64x64, BK=16, 3-stage cp.async, 256 threads, 4x4 per thread.
// Grid (6, 12, 4) = 288 blocks; ~28 KB smem -> multiple CTAs/SM.
// SMEM stage: A [64][20] f32 (5120 B) + B [16][68] f32 (4352 B) = 9472 B
// ============================================================================
#define TA_A_OFF 0
#define TA_B_OFF 5120
#define TA_STG   9472
#define TA_SMEM  (3 * TA_STG)   // 28416

__global__ void __launch_bounds__(256)
tA_gemm(const float* __restrict__ qkv_w)
{
    extern __shared__ char smem[];
    const uint32_t sb = smem_u32(smem);
    float* smf = reinterpret_cast<float*>(smem);
    const int b = blockIdx.z;
    const float* Bm = g_x2 + (size_t)b * C_ * C_;
    const int tm = blockIdx.y * 64, tn = blockIdx.x * 64;
    const int tid = threadIdx.x;
    const int tx = tid & 15, ty = tid >> 4;

    u64 acc[4][2];
#pragma unroll
    for (int i = 0; i < 4; i++) { acc[i][0] = 0ull; acc[i][1] = 0ull; }

    auto ISSUE = [&](int s, int c) {
        const int k0 = c * 16;
        const uint32_t stg = sb + s * TA_STG;
        {   // A tile 64x16 f32 = 256 x 16B chunks, 1 per thread
            int r = tid >> 2, c4 = (tid & 3) << 2;
            cpa16(stg + TA_A_OFF + (uint32_t)((r * 20 + c4) << 2),
                  &qkv_w[(size_t)(tm + r) * C_ + k0 + c4]);
        }
        {   // B tile 16x64 f32 = 256 x 16B chunks, 1 per thread
            int r = tid >> 4, c4 = (tid & 15) << 2;
            cpa16(stg + TA_B_OFF + (uint32_t)((r * 68 + c4) << 2),
                  &Bm[(size_t)(k0 + r) * C_ + tn + c4]);
        }
        CPA_COMMIT();
    };

    auto MMACHUNK = [&](int s) {
        const float* As = smf + (s * TA_STG + TA_A_OFF) / 4;
        const float* Bs = smf + (s * TA_STG + TA_B_OFF) / 4;
#pragma unroll
        for (int kk = 0; kk < 16; kk++) {
            u64 bv0, bv1;
            const u64* bp = reinterpret_cast<const u64*>(&Bs[kk * 68 + tx * 4]);
            bv0 = bp[0]; bv1 = bp[1];
#pragma unroll
            for (int i = 0; i < 4; i++) {
                float a = As[(ty * 4 + i) * 20 + kk];
                u64 av = pk2(a, a);
                acc[i][0] = fma2(av, bv0, acc[i][0]);
                acc[i][1] = fma2(av, bv1, acc[i][1]);
            }
        }
    };

    const int NC = C_ / 16;   // 24
    ISSUE(0, 0);
    ISSUE(1, 1);
    for (int c = 0; c < NC; c++) {
        const int s = c % 3;
        if (c == NC - 1) { CPA_WAIT0(); } else { CPA_WAIT1(); }
        __syncthreads();
        if (c + 2 < NC) ISSUE((c + 2) % 3, c + 2);
        MMACHUNK(s);
    }

    float* T = g_T + (size_t)b * 768 * C_;
#pragma unroll
    for (int i = 0; i < 4; i++) {
        int row = tm + ty * 4 + i;
        float o[4];
        upk2(acc[i][0], o[0], o[1]);
        upk2(acc[i][1], o[2], o[3]);
        *reinterpret_cast<float4*>(&T[(size_t)row * C_ + tn + tx * 4]) =
            make_float4(o[0], o[1], o[2], o[3]);
    }
}

// ============================================================================
// K4: per (b,h): Gqk + norms from T_all, softmax, fold attn into proj_w slice.
// T_all layout: rows 0..383 = q rows (all heads), 384..767 = k rows.
// smem (floats): sWk[48*385] | sG[2304] | sInv[96] | sAttn[2304] | spw[384*49]
// ============================================================================
#define TB_OWK  0
#define TB_OG   18480
#define TB_OINV 20784
#define TB_OATT 20880
#define TB_OPW  23184
#define TB_SMEM ((TB_OPW + 384 * 49) * 4)   // 168000 B

__global__ void __launch_bounds__(256)
tB_kernel(const float* __restrict__ temperature,
          const float* __restrict__ proj_w,
          const float* __restrict__ qkv_w)
{
    extern __shared__ float sm[];
    float* sWk   = sm + TB_OWK;
    float* sG    = sm + TB_OG;
    float* sInv  = sm + TB_OINV;
    float* sAttn = sm + TB_OATT;
    float* spw   = sm + TB_OPW;

    const int bh = blockIdx.x;
    const int b = bh >> 3, h = bh & 7;
    const int tid = threadIdx.x;
    const float* Tq = g_T + (size_t)b * 768 * C_ + (size_t)h * HD_ * C_;
    const float* Tk = g_T + (size_t)b * 768 * C_ + (size_t)(C_ + h * HD_) * C_;

    // load Wk rows (k-side of the head) and proj_w slice
    for (int idx = tid; idx < 48 * C_; idx += 256) {
        int e = idx / C_, k = idx % C_;
        sWk[e * 385 + k] = qkv_w[(size_t)(C_ + h * HD_ + e) * C_ + k];
    }
    for (int idx = tid; idx < 384 * 12; idx += 256) {
        int o = idx / 12, d4 = (idx % 12) * 4;
        float4 v = *reinterpret_cast<const float4*>(&proj_w[(size_t)o * C_ + h * 48 + d4]);
        float* dst = &spw[o * 49 + d4];
        dst[0] = v.x; dst[1] = v.y; dst[2] = v.z; dst[3] = v.w;
    }
    __syncthreads();

    // Gqk[d][e] = Tq[d] . Wk[e]
    for (int idx = tid; idx < 48 * 48; idx += 256) {
        int d = idx / 48, e = idx % 48;
        const float* tr = &Tq[(size_t)d * C_];
        const float* wr = &sWk[e * 385];
        float s = 0.0f;
#pragma unroll 8
        for (int k = 0; k < C_; k++) s += tr[k] * wr[k];
        sG[idx] = s;
    }
    // norms: q: Tq[d].Wq[d]   k: Tk[e].Wk[e]
    if (tid < 96) {
        float s = 0.0f;
        if (tid < 48) {
            const float* tr = &Tq[(size_t)tid * C_];
            const float* wq = &qkv_w[(size_t)(h * HD_ + tid) * C_];
#pragma unroll 8
            for (int k = 0; k < C_; k++) s += tr[k] * wq[k];
        } else {
            int e = tid - 48;
            const float* tr = &Tk[(size_t)e * C_];
            const float* wr = &sWk[e * 385];
#pragma unroll 8
            for (int k = 0; k < C_; k++) s += tr[k] * wr[k];
        }
        sInv[tid] = 1.0f / fmaxf(sqrtf(s), 1e-12f);
    }
    __syncthreads();

    const float temp = temperature[h];
    if (tid < 48) {
        int d = tid;
        float l[48];
        float mx = -1e30f;
#pragma unroll
        for (int e = 0; e < 48; e++) {
            float v = sG[d * 48 + e] * sInv[d] * sInv[48 + e] * temp;
            l[e] = v;
            mx = fmaxf(mx, v);
        }
        float sum = 0.0f;
#pragma unroll
        for (int e = 0; e < 48; e++) { l[e] = expf(l[e] - mx); sum += l[e]; }
        float inv = 1.0f / sum;
#pragma unroll
        for (int e = 0; e < 48; e++) sAttn[d * 48 + e] = l[e] * inv;
    }
    __syncthreads();

    // W_eff[o][h*48+e] = sum_d proj_w[o][h*48+d] * attn[d][e]
    for (int o = tid; o < 384; o += 256) {
        const float* pw = &spw[o * 49];
        float* wout = &g_weff[((size_t)b * C_ + o) * C_ + h * 48];
#pragma unroll
        for (int eb = 0; eb < 6; eb++) {
            float a0 = 0, a1 = 0, a2 = 0, a3 = 0, a4 = 0, a5 = 0, a6 = 0, a7 = 0;
#pragma unroll 8
            for (int d = 0; d < 48; d++) {
                float p = pw[d];
                const float* ar = &sAttn[d * 48 + eb * 8];
                a0 += p * ar[0]; a1 += p * ar[1]; a2 += p * ar[2]; a3 += p * ar[3];
                a4 += p * ar[4]; a5 += p * ar[5]; a6 += p * ar[6]; a7 += p * ar[7];
            }
            wout[eb * 8 + 0] = a0; wout[eb * 8 + 1] = a1;
            wout[eb * 8 + 2] = a2; wout[eb * 8 + 3] = a3;
            wout[eb * 8 + 4] = a4; wout[eb * 8 + 5] = a5;
            wout[eb * 8 + 6] = a6; wout[eb * 8 + 7] = a7;
        }
    }
}

// ============================================================================
// K5: W_final[b] = W_eff[b] (384x384) @ W_v (384x384), output as bf16 planes.
// fp32 f32x2 GEMM, 128x128 tiles, BK=16. Grid (3,3,4).
// ============================================================================
__global__ void __launch_bounds__(256)
wfinal_kernel(const float* __restrict__ qkv_w)
{
    const int BM = 128, BN = 128, BK = 16;
    __shared__ __align__(16) float As[BK][BM];
    __shared__ __align__(16) float Bs[BK][BN];

    const int b = blockIdx.z;
    const float* A = g_weff + (size_t)b * C_ * C_;
    const float* Bm = qkv_w + (size_t)2 * C_ * C_;   // W_v rows 768..1151
    const int tm = blockIdx.y * BM, tn = blockIdx.x * BN;
    const int tid = threadIdx.x;
    const int tx = tid & 15, ty = tid >> 4;

    u64 acc[8][4];
#pragma unroll
    for (int i = 0; i < 8; i++)
#pragma unroll
        for (int p = 0; p < 4; p++) acc[i][p] = 0ull;

    for (int k0 = 0; k0 < C_; k0 += BK) {
#pragma unroll
        for (int i = 0; i < 2; i++) {
            int f4 = tid + 256 * i;
            int r = f4 >> 2, c4 = (f4 & 3) << 2;
            float4 v = *reinterpret_cast<const float4*>(&A[(size_t)(tm + r) * C_ + k0 + c4]);
            As[c4 + 0][r] = v.x; As[c4 + 1][r] = v.y;
            As[c4 + 2][r] = v.z; As[c4 + 3][r] = v.w;
        }
#pragma unroll
        for (int i = 0; i < 2; i++) {
            int f4 = tid + 256 * i;
            int r = f4 >> 5, c4 = (f4 & 31) << 2;
            *reinterpret_cast<float4*>(&Bs[r][c4]) =
                *reinterpret_cast<const float4*>(&Bm[(size_t)(k0 + r) * C_ + tn + c4]);
        }
        __syncthreads();
#pragma unroll
        for (int kk = 0; kk < BK; kk++) {
            u64 av[8];
#pragma unroll
            for (int i = 0; i < 8; i++) { float a = As[kk][ty * 8 + i]; av[i] = pk2(a, a); }
            u64 bv[4];
            const u64* bp = reinterpret_cast<const u64*>(&Bs[kk][tx * 8]);
#pragma unroll
            for (int p = 0; p < 4; p++) bv[p] = bp[p];
#pragma unroll
            for (int i = 0; i < 8; i++)
#pragma unroll
                for (int p = 0; p < 4; p++)
                    acc[i][p] = fma2(av[i], bv[p], acc[i][p]);
        }
        __syncthreads();
    }

#pragma unroll
    for (int i = 0; i < 8; i++) {
        int row = tm + ty * 8 + i;
        float o[8];
#pragma unroll
        for (int p = 0; p < 4; p++) upk2(acc[i][p], o[2 * p], o[2 * p + 1]);
        uint32_t h0, l0, h1, l1, h2, l2, h3, l3;
        split2(h0, l0, o[0], o[1]);
        split2(h1, l1, o[2], o[3]);
        split2(h2, l2, o[4], o[5]);
        split2(h3, l3, o[6], o[7]);
        size_t ro = ((size_t)b * C_ + row) * (C_ / 2) + ((tn + tx * 8) >> 1);
        *reinterpret_cast<uint4*>(g_wf_hi + ro) = make_uint4(h0, h1, h2, h3);
        *reinterpret_cast<uint4*>(g_wf_lo + ro) = make_uint4(l0, l1, l2, l3);
    }
}

// ===========================================================================
// K6: out[b] = W_final[b] (384x384) @ x[b] (384x16384) + proj_b   (fp32 out)
// Tile 128x256, BK=32, warps 2x4 (64x64), 4-stage cp.async.
// ===========================================================================
#define AH_OFF 0
#define AL_OFF 10240
#define BH_OFF 20480
#define BL_OFF 37376
#define STG_SZ 54272
#define GEMM_SMEM (4 * STG_SZ)   // 217088

__global__ void __launch_bounds__(256, 1)
gemm_out(const __nv_bfloat16* __restrict__ Ah, const __nv_bfloat16* __restrict__ Al,
         const __nv_bfloat16* __restrict__ Bh, const __nv_bfloat16* __restrict__ Bl,
         int M, int N, int K, long long sA, long long sB,
         float* __restrict__ Of, long long sC, const float* __restrict__ bias)
{
    extern __shared__ char smem[];
    const uint32_t sb = smem_u32(smem);
    const int tid = threadIdx.x;
    const int wid = tid >> 5, lane = tid & 31;

    const int z = blockIdx.z;
    Ah += (size_t)z * sA;  Al += (size_t)z * sA;
    Bh += (size_t)z * sB;  Bl += (size_t)z * sB;
    const int tm = blockIdx.x * 128, tn = blockIdx.y * 256;
    const int warp_m = (wid >> 2) * 64, warp_n = (wid & 3) * 64;

    float acc[4][8][4];
#pragma unroll
    for (int i = 0; i < 4; i++)
#pragma unroll
        for (int j = 0; j < 8; j++)
#pragma unroll
            for (int p = 0; p < 4; p++) acc[i][j][p] = 0.0f;

    auto ISSUE = [&](int s, int c) {
        const int k0 = c * 32;
        const uint32_t stg = sb + s * STG_SZ;
#pragma unroll
        for (int i = 0; i < 4; i++) {
            int id = tid + 256 * i;
            int pl = id >> 9, rem = id & 511, row = rem >> 2, ch = rem & 3;
            const __nv_bfloat16* src = (pl ? Al : Ah) + (size_t)(tm + row) * K + k0 + ch * 8;
            cpa16(stg + AH_OFF + pl * (AL_OFF - AH_OFF) + (uint32_t)((row * 40 + ch * 8) << 1), src);
        }
#pragma unroll
        for (int i = 0; i < 8; i++) {
            int id = tid + 256 * i;
            int pl = id >> 10, rem = id & 1023, row = rem >> 5, ch = rem & 31;
            const __nv_bfloat16* src = (pl ? Bl : Bh) + (size_t)(k0 + row) * N + tn + ch * 8;
            cpa16(stg + BH_OFF + pl * (BL_OFF - BH_OFF) + (uint32_t)((row * 264 + ch * 8) << 1), src);
        }
        CPA_COMMIT();
    };

    auto MMASTEP = [&](int s, int ks) {
        const uint32_t stg = sb + s * STG_SZ;
        uint32_t bh[8][2], bl[8][2];
        {
            uint32_t krow = (uint32_t)(ks * 16 + (lane & 7) + (((lane >> 3) & 1) << 3));
            uint32_t ncol = (uint32_t)(warp_n + ((lane >> 4) << 3));
            uint32_t bd  = stg + BH_OFF + ((krow * 264 + ncol) << 1);
            uint32_t bdl = bd + (BL_OFF - BH_OFF);
            uint32_t r4[4];
#pragma unroll
            for (int j = 0; j < 4; j++) {
                ldsm4t(r4, bd + j * 32);
                bh[2 * j][0] = r4[0]; bh[2 * j][1] = r4[1];
                bh[2 * j + 1][0] = r4[2]; bh[2 * j + 1][1] = r4[3];
            }
#pragma unroll
            for (int j = 0; j < 4; j++) {
                ldsm4t(r4, bdl + j * 32);
                bl[2 * j][0] = r4[0]; bl[2 * j][1] = r4[1];
                bl[2 * j + 1][0] = r4[2]; bl[2 * j + 1][1] = r4[3];
            }
        }
        const uint32_t arow = (uint32_t)(warp_m + (lane & 15));
        const uint32_t akoff = (uint32_t)(ks * 16 + ((lane >> 4) << 3));
#pragma unroll
        for (int mf = 0; mf < 4; mf++) {
            uint32_t ah[4], al[4];
            uint32_t ad = stg + AH_OFF + (((arow + mf * 16) * 40 + akoff) << 1);
            ldsm4(ah, ad);
            ldsm4(al, ad + (AL_OFF - AH_OFF));
#pragma unroll
            for (int nf = 0; nf < 8; nf++) {
                mma16816(acc[mf][nf], ah, bh[nf]);
                mma16816(acc[mf][nf], ah, bl[nf]);
                mma16816(acc[mf][nf], al, bh[nf]);
            }
        }
    };

    const int NC = K >> 5;   // 12
    ISSUE(0, 0);
    ISSUE(1, 1);
    ISSUE(2, 2);
    for (int c = 0; c < NC; c++) {
        const int s = c & 3;
        const int left = NC - c;
        if (left >= 3) { CPA_WAIT2(); } else if (left == 2) { CPA_WAIT1(); } else { CPA_WAIT0(); }
        __syncthreads();
        if (c + 3 < NC) ISSUE((c + 3) & 3, c + 3);
        MMASTEP(s, 0);
        MMASTEP(s, 1);
    }
    __syncthreads();

    float* cs = reinterpret_cast<float*>(smem);
    const int g = lane >> 2, t2 = (lane & 3) * 2;
#pragma unroll
    for (int mf = 0; mf < 4; mf++)
#pragma unroll
        for (int nf = 0; nf < 8; nf++) {
            int r0 = warp_m + mf * 16 + g;
            int c0 = warp_n + nf * 8 + t2;
            cs[r0 * 260 + c0]           = acc[mf][nf][0];
            cs[r0 * 260 + c0 + 1]       = acc[mf][nf][1];
            cs[(r0 + 8) * 260 + c0]     = acc[mf][nf][2];
            cs[(r0 + 8) * 260 + c0 + 1] = acc[mf][nf][3];
        }
    __syncthreads();

    const int r = tid >> 1, cb = (tid & 1) * 128;
    const float* ip = &cs[r * 260 + cb];
    float* op = Of + (size_t)z * sC + (size_t)(tm + r) * N + tn + cb;
    const float bval = bias[tm + r];
#pragma unroll
    for (int j = 0; j < 32; j++) {
        float4 v = make_float4(ip[4 * j] + bval, ip[4 * j + 1] + bval,
                               ip[4 * j + 2] + bval, ip[4 * j + 3] + bval);
        reinterpret_cast<float4*>(op)[j] = v;
    }
}

// ============================================================================
extern "C" void kernel_launch(void* const* d_in, const int* in_sizes, int n_in,
                              void* d_out, int out_size)
{
    const float* x           = (const float*)d_in[0];
    const float* qkv_w       = (const float*)d_in[1];
    const float* proj_w      = (const float*)d_in[2];
    const float* proj_b      = (const float*)d_in[3];
    const float* temperature = (const float*)d_in[4];
    float* out = (float*)d_out;

    void* p;
    cudaGetSymbolAddress(&p, g_x_hi);  uint32_t* x_hi = (uint32_t*)p;
    cudaGetSymbolAddress(&p, g_x_lo);  uint32_t* x_lo = (uint32_t*)p;
    cudaGetSymbolAddress(&p, g_wf_hi); uint32_t* wf_hi = (uint32_t*)p;
    cudaGetSymbolAddress(&p, g_wf_lo); uint32_t* wf_lo = (uint32_t*)p;

    cudaFuncSetAttribute((const void*)x2_cp,
                         cudaFuncAttributeMaxDynamicSharedMemorySize, X2_SMEM);
    cudaFuncSetAttribute((const void*)tA_gemm,
                         cudaFuncAttributeMaxDynamicSharedMemorySize, TA_SMEM);
    cudaFuncSetAttribute((const void*)tB_kernel,
                         cudaFuncAttributeMaxDynamicSharedMemorySize, TB_SMEM);
    cudaFuncSetAttribute((const void*)gemm_out,
                         cudaFuncAttributeMaxDynamicSharedMemorySize, GEMM_SMEM);

    // K0: x -> bf16 hi/lo planes
    split_planes<<<2048, 256>>>((const float2*)x, x_hi, x_lo, B_ * C_ * HW_ / 2);

    // K1: X2 upper-block partials (Gram of x)
    x2_cp<<<dim3(6 * NS2, B_), 256, X2_SMEM>>>(
        (const __nv_bfloat16*)x_hi, (const __nv_bfloat16*)x_lo);

    // K2: reduce + mirror
    x2_reduce<<<B_ * C_ * C_ / 256, 256>>>();

    // K3: T_all = qkv_w[0:768] @ X2  (f32x2 GEMM, 3-stage cp.async)
    tA_gemm<<<dim3(6, 12, B_), 256, TA_SMEM>>>(qkv_w);

    // K4: Gram->softmax->W_eff fold
    tB_kernel<<<B_ * NH_, 256, TB_SMEM>>>(temperature, proj_w, qkv_w);

    // K5: W_final = W_eff @ W_v  -> bf16 planes
    wfinal_kernel<<<dim3(3, 3, B_), 256>>>(qkv_w);

    // K6: out = W_final @ x + proj_b
    gemm_out<<<dim3(C_ / 128, HW_ / 256, B_), 256, GEMM_SMEM>>>(
        (const __nv_bfloat16*)wf_hi, (const __nv_bfloat16*)wf_lo,
        (const __nv_bfloat16*)x_hi, (const __nv_bfloat16*)x_lo,
        C_, HW_, C_, (long long)C_ * C_, (long long)C_ * HW_,
        out, (long long)C_ * HW_, proj_b);
}